// round 9
// baseline (speedup 1.0000x reference)
#include <cuda_runtime.h>
#include <math.h>

#define BB 64
#define NCAPC 64
#define LVC 197
#define NSP 196
#define LTC 32
#define CCH 512
#define NKEEP 98
#define KEEPEDC 49
#define HIDC 102
#define LN_EPSF 1e-5f

typedef unsigned long long ull;

__device__ float g_inv_img[BB * LVC];
__device__ float g_attn_x[BB * NSP];
__device__ float g_attn_y[(size_t)NCAPC * BB * NSP];     // [i][r], r = b*196+j
__device__ float g_W0[(size_t)BB * NSP * KEEPEDC];
__device__ float g_CAT[(size_t)NCAPC * 96 * CCH];
__device__ float g_gloT[CCH * NCAPC];

__device__ __forceinline__ float warpReduceSum(float v) {
    #pragma unroll
    for (int o = 16; o > 0; o >>= 1) v += __shfl_xor_sync(0xffffffffu, v, o);
    return v;
}
__device__ __forceinline__ float warpReduceMax(float v) {
    #pragma unroll
    for (int o = 16; o > 0; o >>= 1) v = fmaxf(v, __shfl_xor_sync(0xffffffffu, v, o));
    return v;
}
__device__ __forceinline__ void fma2(ull& acc, ull a, ull b) {
    asm("fma.rn.f32x2 %0, %1, %2, %0;" : "+l"(acc) : "l"(a), "l"(b));
}
__device__ __forceinline__ ull pack2(float a, float b) {
    ull r; asm("mov.b64 %0, {%1, %2};" : "=l"(r) : "f"(a), "f"(b)); return r;
}
__device__ __forceinline__ float2 unpack2(ull v) {
    float2 f; asm("mov.b64 {%0, %1}, %2;" : "=f"(f.x), "=f"(f.y) : "l"(v)); return f;
}

// ---------------- K1: inverse norms ----------------
__global__ void k_inv(const float* __restrict__ img) {
    int r = blockIdx.x;
    const float* x = img + (size_t)r * CCH;
    int tid = threadIdx.x;
    float ss = 0.f;
    for (int c = tid; c < CCH; c += 128) { float v = x[c]; ss += v * v; }
    __shared__ float red[4];
    ss = warpReduceSum(ss);
    if ((tid & 31) == 0) red[tid >> 5] = ss;
    __syncthreads();
    if (tid == 0) g_inv_img[r] = 1.f / fmaxf(sqrtf(red[0]+red[1]+red[2]+red[3]), 1e-12f);
}

// ---------------- K2: attn_x ----------------
__global__ void k_attnx(const float* __restrict__ img) {
    int r = blockIdx.x; int b = r / NSP; int j = r - b * NSP;
    const float* x0 = img + (size_t)b * LVC * CCH;
    const float* xj = x0 + (size_t)(1 + j) * CCH;
    int tid = threadIdx.x;
    float d = 0.f;
    for (int c = tid; c < CCH; c += 128) d += x0[c] * xj[c];
    __shared__ float red[4];
    d = warpReduceSum(d);
    if ((tid & 31) == 0) red[tid >> 5] = d;
    __syncthreads();
    if (tid == 0) {
        float t = red[0]+red[1]+red[2]+red[3];
        g_attn_x[r] = t * g_inv_img[b * LVC] * g_inv_img[b * LVC + 1 + j];
    }
}

// ---------------- K3: cap_norm rows + gloT ----------------
__global__ void k_cap(const float* __restrict__ cap) {
    int r = blockIdx.x; int i = r / LTC; int t = r - i * LTC;
    const float* x = cap + (size_t)r * CCH;
    int tid = threadIdx.x;
    float ss = 0.f;
    for (int c = tid; c < CCH; c += 128) { float v = x[c]; ss += v * v; }
    __shared__ float red[4]; __shared__ float s_inv;
    ss = warpReduceSum(ss);
    if ((tid & 31) == 0) red[tid >> 5] = ss;
    __syncthreads();
    if (tid == 0) s_inv = 1.f / fmaxf(sqrtf(red[0]+red[1]+red[2]+red[3]), 1e-12f);
    __syncthreads();
    float inv = s_inv;
    float* dst = g_CAT + ((size_t)i * 96 + t) * CCH;
    for (int c = tid; c < CCH; c += 128) {
        float v = x[c] * inv;
        dst[c] = v;
        if (t == 0) g_gloT[c * NCAPC + i] = v;
    }
}

// ---------------- K4: CAT rows 32..95 = cap_norm @ W + b ----------------
__global__ __launch_bounds__(256) void k_capW(
    const float* __restrict__ wi2t, const float* __restrict__ bi2t,
    const float* __restrict__ wt2i, const float* __restrict__ bt2i) {
    extern __shared__ float s_xT[];     // [ci][34]
    int bx = blockIdx.x;
    int i = bx >> 2; int which = (bx >> 1) & 1; int halfid = bx & 1;
    int tid = threadIdx.x;
    int col = halfid * 256 + tid;
    const float* src = g_CAT + (size_t)i * 96 * CCH;
    for (int idx = tid; idx < LTC * CCH; idx += 256) {
        int t = idx >> 9; int c = idx & 511;
        s_xT[c * 34 + t] = src[idx];
    }
    __syncthreads();
    const float* W = which ? wt2i : wi2t;
    const float* bias = which ? bt2i : bi2t;
    ull acc[16];
    #pragma unroll
    for (int p = 0; p < 16; p++) acc[p] = 0ull;
    float w = W[col];
    for (int ci = 0; ci < CCH; ci++) {
        float wn = (ci < CCH - 1) ? W[(size_t)(ci + 1) * CCH + col] : 0.f;
        ull ww = pack2(w, w);
        const ull* xr = (const ull*)(s_xT + ci * 34);
        #pragma unroll
        for (int p = 0; p < 16; p++) fma2(acc[p], xr[p], ww);
        w = wn;
    }
    float bb = bias[col];
    float* dst = g_CAT + ((size_t)i * 96 + 32 + which * 32) * CCH;
    #pragma unroll
    for (int p = 0; p < 16; p++) {
        float2 f = unpack2(acc[p]);
        dst[(size_t)(2 * p) * CCH + col]     = f.x + bb;
        dst[(size_t)(2 * p + 1) * CCH + col] = f.y + bb;
    }
}

// ---------------- K5: W0, 16 tokens per block ----------------
__global__ __launch_bounds__(256) void k_W0(const float* __restrict__ img,
                     const float* __restrict__ gamma, const float* __restrict__ beta,
                     const float* __restrict__ w1, const float* __restrict__ b1,
                     const float* __restrict__ w2, const float* __restrict__ b2) {
    __shared__ float s_y[16 * CCH];
    __shared__ float s_h[16 * 104];
    int tid = threadIdx.x;
    int lane = tid & 31, wid = tid >> 5;
    int r0 = blockIdx.x * 16;
    #pragma unroll
    for (int rr = wid; rr < 16; rr += 8) {
        int tok = r0 + rr;
        int b = tok / NSP; int j = tok - b * NSP;
        const float* x = img + ((size_t)b * LVC + 1 + j) * CCH;
        float s = 0.f, ss = 0.f;
        for (int c = lane; c < CCH; c += 32) { float v = x[c]; s += v; ss += v * v; }
        s = warpReduceSum(s); ss = warpReduceSum(ss);
        float mean = s * (1.f / CCH);
        float var = ss * (1.f / CCH) - mean * mean;
        float rstd = 1.f / sqrtf(var + LN_EPSF);
        for (int c = lane; c < CCH; c += 32)
            s_y[rr * CCH + c] = (x[c] - mean) * rstd * gamma[c] + beta[c];
    }
    __syncthreads();
    for (int task = tid; task < 16 * HIDC; task += 256) {
        int row = task / HIDC; int col = task - row * HIDC;
        float acc = b1[col];
        const float* yr = s_y + row * CCH;
        #pragma unroll 8
        for (int c = 0; c < CCH; c++) acc += yr[c] * w1[(size_t)c * HIDC + col];
        s_h[row * 104 + col] = 0.5f * acc * (1.f + erff(acc * 0.70710678118654752f));
    }
    __syncthreads();
    for (int task = tid; task < 16 * KEEPEDC; task += 256) {
        int row = task / KEEPEDC; int col = task - row * KEEPEDC;
        float acc = b2[col];
        const float* hr = s_h + row * 104;
        #pragma unroll 6
        for (int c = 0; c < HIDC; c++) acc += hr[c] * w2[c * KEEPEDC + col];
        g_W0[(size_t)(r0 + row) * KEEPEDC + col] = acc;
    }
}

// ---------------- K6: attn_y tiled GEMM ----------------
__global__ __launch_bounds__(256) void k_attn_y(const float* __restrict__ img) {
    __shared__ float s_x[32 * 68];
    __shared__ float s_g[32 * 68];
    __shared__ int   s_off[64];
    __shared__ float s_inv[64];
    int tid = threadIdx.x;
    int r0 = blockIdx.x * 64;
    if (tid < 64) {
        int tok = r0 + tid;
        int b = tok / NSP; int j = tok - b * NSP;
        s_off[tid] = (b * LVC + 1 + j) * CCH;
        s_inv[tid] = g_inv_img[b * LVC + 1 + j];
    }
    __syncthreads();
    int tx = tid & 15, ty = tid >> 4;
    int i0 = tx * 4, t0 = ty * 4;
    float acc[4][4];
    #pragma unroll
    for (int a = 0; a < 4; a++)
        #pragma unroll
        for (int c = 0; c < 4; c++) acc[a][c] = 0.f;
    for (int c0 = 0; c0 < CCH; c0 += 32) {
        {
            int tk = tid >> 2; int cc0 = (tid & 3) * 8;
            const float* p = img + s_off[tk] + c0 + cc0;
            float4 v0 = *(const float4*)p;
            float4 v1 = *(const float4*)(p + 4);
            s_x[(cc0 + 0) * 68 + tk] = v0.x; s_x[(cc0 + 1) * 68 + tk] = v0.y;
            s_x[(cc0 + 2) * 68 + tk] = v0.z; s_x[(cc0 + 3) * 68 + tk] = v0.w;
            s_x[(cc0 + 4) * 68 + tk] = v1.x; s_x[(cc0 + 5) * 68 + tk] = v1.y;
            s_x[(cc0 + 6) * 68 + tk] = v1.z; s_x[(cc0 + 7) * 68 + tk] = v1.w;
        }
        {
            int cc = tid >> 3; int ii = (tid & 7) * 8;
            const float* p = g_gloT + (size_t)(c0 + cc) * NCAPC + ii;
            *(float4*)(s_g + cc * 68 + ii)     = *(const float4*)p;
            *(float4*)(s_g + cc * 68 + ii + 4) = *(const float4*)(p + 4);
        }
        __syncthreads();
        for (int cc = 0; cc < 32; cc++) {
            float4 gv = *(const float4*)(s_g + cc * 68 + i0);
            float4 xv = *(const float4*)(s_x + cc * 68 + t0);
            float xa[4] = {xv.x, xv.y, xv.z, xv.w};
            float gb[4] = {gv.x, gv.y, gv.z, gv.w};
            #pragma unroll
            for (int a = 0; a < 4; a++)
                #pragma unroll
                for (int c = 0; c < 4; c++) acc[a][c] += xa[a] * gb[c];
        }
        __syncthreads();
    }
    #pragma unroll
    for (int a = 0; a < 4; a++) {
        float inv = s_inv[t0 + a];
        #pragma unroll
        for (int c = 0; c < 4; c++)
            g_attn_y[(size_t)(i0 + c) * (BB * NSP) + r0 + t0 + a] = acc[a][c] * inv;
    }
}

// ---------------- K7: per-pair fused kernel (512 threads) ----------------
#define ST_ROW 516
#define OFF_ST 0
#define SZ_ST (51 * ST_ROW)                  // 26316
#define OFF_U SZ_ST
#define OFF_A OFF_U                          // [jj][50]: 98*50 = 4900
#define OFF_WNON (OFF_U + 98 * 50)           // 98
#define OFF_E OFF_U                          // 96*136 = 13056
#define OFF_G (OFF_U + 96 * 136)             // 96*51 = 4896
#define OFF_CM (OFF_G + 96 * 51)
#define OFF_CZ (OFF_CM + 51)
#define OFF_RM (OFF_CZ + 51)
#define OFF_RZ (OFF_RM + 32)
#define SZ_U (96 * 136 + 96 * 51 + 51 + 51 + 32 + 32)   // 18118
#define OFF_SCORE (OFF_U + SZ_U)             // 44434
#define OFF_ORDER (OFF_SCORE + 196)
#define OFF_RED (OFF_ORDER + 196)
#define OFF_SCAL (OFF_RED + 16)
#define SMEM_FLOATS (OFF_SCAL + 4)           // 44846 floats = 179384 B

__global__ __launch_bounds__(512, 1) void k_pair(
    const float* __restrict__ img,
    const float* __restrict__ aggr_scale_p,
    const float* __restrict__ temp_p,
    float* __restrict__ out) {
    extern __shared__ float sm[];
    float* s_st    = sm + OFF_ST;
    float* s_A     = sm + OFF_A;
    float* s_wnon  = sm + OFF_WNON;
    float* s_E     = sm + OFF_E;
    float* s_G     = sm + OFF_G;
    float* s_cm    = sm + OFF_CM;
    float* s_cz    = sm + OFF_CZ;
    float* s_rm    = sm + OFF_RM;
    float* s_rz    = sm + OFF_RZ;
    float* s_score = sm + OFF_SCORE;
    int*   s_order = (int*)(sm + OFF_ORDER);
    float* s_red   = sm + OFF_RED;
    float* s_scal  = sm + OFF_SCAL;

    int pair = blockIdx.x;
    int i = pair & (NCAPC - 1);
    int b = pair >> 6;
    int tid = threadIdx.x;
    int lane = tid & 31, wid = tid >> 5;

    // ---- 1. scores ----
    if (tid < NSP) {
        s_score[tid] = g_attn_x[b * NSP + tid]
                     + g_attn_y[(size_t)i * (BB * NSP) + b * NSP + tid];
    }
    __syncthreads();

    // ---- 2. stable rank ----
    if (tid < NSP) {
        float sj = s_score[tid];
        int rank = 0;
        for (int j2 = 0; j2 < NSP; j2++) {
            float s2 = s_score[j2];
            rank += (s2 > sj) || (s2 == sj && j2 < tid);
        }
        s_order[rank] = tid;
    }
    __syncthreads();

    // ---- 3a. softmax over nonkeep scores ----
    if (tid < 98) s_wnon[tid] = s_score[s_order[NKEEP + tid]];
    __syncthreads();
    if (wid == 0) {
        float m = -INFINITY;
        for (int t = lane; t < 98; t += 32) m = fmaxf(m, s_wnon[t]);
        m = warpReduceMax(m);
        if (lane == 0) s_scal[0] = m;
    }
    __syncthreads();
    if (tid < 98) s_wnon[tid] = expf(s_wnon[tid] - s_scal[0]);
    __syncthreads();
    if (wid == 0) {
        float z = 0.f;
        for (int t = lane; t < 98; t += 32) z += s_wnon[t];
        z = warpReduceSum(z);
        if (lane == 0) s_scal[1] = 1.f / z;
    }
    // ---- 3b. gather A[jj][50] (49 weights + zero pad) ----
    {
        float ascale = aggr_scale_p[0];
        for (int idx = tid; idx < NKEEP * KEEPEDC; idx += 512) {
            int jj = idx / KEEPEDC; int k = idx - jj * KEEPEDC;
            s_A[jj * 50 + k] = g_W0[((size_t)b * NSP + s_order[jj]) * KEEPEDC + k] * ascale;
        }
        if (tid < 98) s_A[tid * 50 + 49] = 0.f;
    }
    __syncthreads();
    // ---- 3c. per-k softmax over 98 keep entries (16 warps) ----
    for (int k = wid; k < KEEPEDC; k += 16) {
        float km = -INFINITY;
        for (int jj = lane; jj < NKEEP; jj += 32) km = fmaxf(km, s_A[jj * 50 + k]);
        km = warpReduceMax(km);
        float kz = 0.f;
        for (int jj = lane; jj < NKEEP; jj += 32) {
            float e = expf(s_A[jj * 50 + k] - km);
            s_A[jj * 50 + k] = e; kz += e;
        }
        kz = warpReduceSum(kz);
        float inv = 1.f / kz;
        for (int jj = lane; jj < NKEEP; jj += 32) s_A[jj * 50 + k] *= inv;
    }
    __syncthreads();

    // ---- 4. aggr + extra + cls -> unnormalized sel_tok (1 channel/thread) ----
    {
        const float* spbase = img + ((size_t)b * LVC + 1) * CCH;
        int c = tid;
        ull acc[25];
        #pragma unroll
        for (int kk = 0; kk < 25; kk++) acc[kk] = 0ull;
        float x0 = spbase[(size_t)s_order[0] * CCH + c];
        float x1 = spbase[(size_t)s_order[1] * CCH + c];
        for (int jj = 0; jj < NKEEP; jj++) {
            float xn = spbase[(size_t)s_order[jj + 2] * CCH + c];   // jj+2 <= 99 < 196
            ull xx = pack2(x0, x0);
            const ull* arow = (const ull*)(s_A + jj * 50);
            #pragma unroll
            for (int kk = 0; kk < 25; kk++) fma2(acc[kk], arow[kk], xx);
            x0 = x1; x1 = xn;
        }
        float wacc = 0.f;
        for (int jj = NKEEP; jj < NSP; jj++) {
            int jn = (jj + 2 < NSP) ? jj + 2 : NSP - 1;
            float xn = spbase[(size_t)s_order[jn] * CCH + c];
            wacc += s_wnon[jj - NKEEP] * x0;
            x0 = x1; x1 = xn;
        }
        s_st[0 * ST_ROW + c] = img[(size_t)b * LVC * CCH + c];
        #pragma unroll
        for (int kk = 0; kk < 25; kk++) {
            float2 f = unpack2(acc[kk]);
            s_st[(1 + 2 * kk) * ST_ROW + c] = f.x;
            if (2 * kk + 1 < KEEPEDC) s_st[(2 + 2 * kk) * ST_ROW + c] = f.y;
        }
        s_st[50 * ST_ROW + c] = wacc * s_scal[1];
    }
    __syncthreads();

    // ---- 5. L2-normalize 51 rows (16 warps) ----
    for (int row = wid; row < 51; row += 16) {
        float ssq = 0.f;
        for (int cc = lane; cc < CCH; cc += 32) { float v = s_st[row * ST_ROW + cc]; ssq += v * v; }
        ssq = warpReduceSum(ssq);
        float inv = 1.f / fmaxf(sqrtf(ssq), 1e-12f);
        for (int cc = lane; cc < CCH; cc += 32) s_st[row * ST_ROW + cc] *= inv;
    }
    __syncthreads();

    // ---- 6. G = CAT_i @ sel_tok^T (96x51): 24x17 threads, 4t x 3l tiles ----
    {
        const float* E = g_CAT + (size_t)i * 96 * CCH;
        ull acc2[4][3];
        #pragma unroll
        for (int a = 0; a < 4; a++)
            #pragma unroll
            for (int l = 0; l < 3; l++) acc2[a][l] = 0ull;
        int lgrp = tid % 17, tq = tid / 17;
        bool active = (tq < 24);
        int l0 = lgrp * 3, t0 = tq * 4;
        for (int ch = 0; ch < 4; ch++) {
            int c0 = ch * 128;
            for (int idx = tid * 4; idx < 96 * 128; idx += 2048) {
                int t = idx >> 7; int cc = idx & 127;
                *(float4*)(s_E + t * 136 + cc) = *(const float4*)(E + (size_t)t * CCH + c0 + cc);
            }
            __syncthreads();
            if (active) {
                for (int cc = 0; cc < 128; cc += 4) {
                    ulonglong2 st0 = *(const ulonglong2*)(s_st + (l0 + 0) * ST_ROW + c0 + cc);
                    ulonglong2 st1 = *(const ulonglong2*)(s_st + (l0 + 1) * ST_ROW + c0 + cc);
                    ulonglong2 st2 = *(const ulonglong2*)(s_st + (l0 + 2) * ST_ROW + c0 + cc);
                    #pragma unroll
                    for (int a = 0; a < 4; a++) {
                        ulonglong2 e = *(const ulonglong2*)(s_E + (t0 + a) * 136 + cc);
                        fma2(acc2[a][0], e.x, st0.x); fma2(acc2[a][0], e.y, st0.y);
                        fma2(acc2[a][1], e.x, st1.x); fma2(acc2[a][1], e.y, st1.y);
                        fma2(acc2[a][2], e.x, st2.x); fma2(acc2[a][2], e.y, st2.y);
                    }
                }
            }
            __syncthreads();
        }
        if (active) {
            #pragma unroll
            for (int a = 0; a < 4; a++)
                #pragma unroll
                for (int l = 0; l < 3; l++) {
                    float2 p = unpack2(acc2[a][l]);
                    s_G[(t0 + a) * 51 + l0 + l] = p.x + p.y;
                }
        }
    }
    __syncthreads();

    // ---- 7. softmaxes + final reduction ----
    float invtemp = 1.f / temp_p[0];
    if (tid < 51) {
        int l = tid;
        float cm = -INFINITY;
        for (int t = 0; t < 32; t++) cm = fmaxf(cm, s_G[(32 + t) * 51 + l] * invtemp);
        float cz = 0.f;
        for (int t = 0; t < 32; t++) cz += expf(s_G[(32 + t) * 51 + l] * invtemp - cm);
        s_cm[l] = cm; s_cz[l] = cz;
    } else if (tid >= 64 && tid < 96) {
        int t = tid - 64;
        float rm = -INFINITY;
        for (int l = 0; l < 51; l++) rm = fmaxf(rm, s_G[(64 + t) * 51 + l] * invtemp);
        float rz = 0.f;
        for (int l = 0; l < 51; l++) rz += expf(s_G[(64 + t) * 51 + l] * invtemp - rm);
        s_rm[t] = rm; s_rz[t] = rz;
    }
    __syncthreads();
    float part = 0.f;
    for (int idx = tid; idx < 32 * 51; idx += 512) {
        int t = idx / 51; int l = idx - t * 51;
        float g = s_G[t * 51 + l];
        float c2i = (g >= 0.f) ? g : 0.1f * g;
        float li = s_G[(32 + t) * 51 + l] * invtemp;
        float lt = s_G[(64 + t) * 51 + l] * invtemp;
        float ai = expf(li - s_cm[l]) / s_cz[l];
        float at = expf(lt - s_rm[t]) / s_rz[t];
        part += c2i * (ai * (1.f / 51.f) + at * (1.f / 32.f));
    }
    part = warpReduceSum(part);
    if (lane == 0) s_red[wid] = part;
    __syncthreads();
    if (tid == 0) {
        float s = 0.f;
        for (int w = 0; w < 16; w++) s += s_red[w];
        out[b * NCAPC + i] = s;
    }
}

// ---------------- launch ----------------
extern "C" void kernel_launch(void* const* d_in, const int* in_sizes, int n_in,
                              void* d_out, int out_size) {
    const float* img    = (const float*)d_in[0];
    const float* cap    = (const float*)d_in[1];
    const float* gamma  = (const float*)d_in[3];
    const float* beta   = (const float*)d_in[4];
    const float* w1     = (const float*)d_in[5];
    const float* b1     = (const float*)d_in[6];
    const float* w2     = (const float*)d_in[7];
    const float* b2     = (const float*)d_in[8];
    const float* ascale = (const float*)d_in[9];
    const float* wi2t   = (const float*)d_in[10];
    const float* bi2t   = (const float*)d_in[11];
    const float* wt2i   = (const float*)d_in[12];
    const float* bt2i   = (const float*)d_in[13];
    const float* temp   = (const float*)d_in[14];
    float* out = (float*)d_out;

    cudaFuncSetAttribute(k_capW, cudaFuncAttributeMaxDynamicSharedMemorySize, 512 * 34 * 4);
    cudaFuncSetAttribute(k_pair, cudaFuncAttributeMaxDynamicSharedMemorySize, SMEM_FLOATS * 4);

    k_inv<<<BB * LVC, 128>>>(img);
    k_cap<<<NCAPC * LTC, 128>>>(cap);
    k_attnx<<<BB * NSP, 128>>>(img);
    k_capW<<<NCAPC * 4, 256, 512 * 34 * 4>>>(wi2t, bi2t, wt2i, bt2i);
    k_W0<<<(BB * NSP) / 16, 256>>>(img, gamma, beta, w1, b1, w2, b2);
    k_attn_y<<<(BB * NSP) / 64, 256>>>(img);
    k_pair<<<NCAPC * BB, 512, SMEM_FLOATS * 4>>>(img, ascale, temp, out);
}

// round 12
// speedup vs baseline: 1.4237x; 1.4237x over previous
#include <cuda_runtime.h>
#include <math.h>

#define BB 64
#define NCAPC 64
#define LVC 197
#define NSP 196
#define LTC 32
#define CCH 512
#define NKEEP 98
#define KEEPEDC 49
#define HIDC 102
#define LN_EPSF 1e-5f

typedef unsigned long long ull;

__device__ float g_inv_img[BB * LVC];
__device__ float g_attn_x[BB * NSP];
__device__ float g_attn_y[(size_t)NCAPC * BB * NSP];     // [i][r]
__device__ float g_W0[(size_t)BB * NSP * KEEPEDC];
__device__ float g_CAT[(size_t)NCAPC * 96 * CCH];
__device__ float g_gloT[CCH * NCAPC];
__device__ float g_img32[(size_t)BB * 200 * CCH];        // tf32-bit img_sp, 196 rows + 4 zero rows per image

__device__ __forceinline__ float warpReduceSum(float v) {
    #pragma unroll
    for (int o = 16; o > 0; o >>= 1) v += __shfl_xor_sync(0xffffffffu, v, o);
    return v;
}
__device__ __forceinline__ float warpReduceMax(float v) {
    #pragma unroll
    for (int o = 16; o > 0; o >>= 1) v = fmaxf(v, __shfl_xor_sync(0xffffffffu, v, o));
    return v;
}
__device__ __forceinline__ void fma2(ull& acc, ull a, ull b) {
    asm("fma.rn.f32x2 %0, %1, %2, %0;" : "+l"(acc) : "l"(a), "l"(b));
}
__device__ __forceinline__ ull pack2(float a, float b) {
    ull r; asm("mov.b64 %0, {%1, %2};" : "=l"(r) : "f"(a), "f"(b)); return r;
}
__device__ __forceinline__ float2 unpack2(ull v) {
    float2 f; asm("mov.b64 {%0, %1}, %2;" : "=f"(f.x), "=f"(f.y) : "l"(v)); return f;
}
__device__ __forceinline__ unsigned f2tf(float f) {
    unsigned u; asm("cvt.rna.tf32.f32 %0, %1;" : "=r"(u) : "f"(f)); return u;
}
__device__ __forceinline__ void mma_tf32(float* d, unsigned a0, unsigned a1, unsigned a2, unsigned a3,
                                         unsigned b0, unsigned b1) {
    asm volatile("mma.sync.aligned.m16n8k8.row.col.f32.tf32.tf32.f32 "
                 "{%0,%1,%2,%3}, {%4,%5,%6,%7}, {%8,%9}, {%0,%1,%2,%3};"
                 : "+f"(d[0]), "+f"(d[1]), "+f"(d[2]), "+f"(d[3])
                 : "r"(a0), "r"(a1), "r"(a2), "r"(a3), "r"(b0), "r"(b1));
}

// ---------------- K1: inverse norms ----------------
__global__ void k_inv(const float* __restrict__ img) {
    int r = blockIdx.x;
    const float* x = img + (size_t)r * CCH;
    int tid = threadIdx.x;
    float ss = 0.f;
    for (int c = tid; c < CCH; c += 128) { float v = x[c]; ss += v * v; }
    __shared__ float red[4];
    ss = warpReduceSum(ss);
    if ((tid & 31) == 0) red[tid >> 5] = ss;
    __syncthreads();
    if (tid == 0) g_inv_img[r] = 1.f / fmaxf(sqrtf(red[0]+red[1]+red[2]+red[3]), 1e-12f);
}

// ---------------- K1b: img_sp -> tf32 padded [b][200][512] ----------------
__global__ void k_img32(const float* __restrict__ img) {
    int r = blockIdx.x;                 // b*200 + k
    int b = r / 200; int k = r - b * 200;
    float* dst = g_img32 + (size_t)r * CCH;
    int c = threadIdx.x * 4;
    if (k < NSP) {
        const float* src = img + ((size_t)b * LVC + 1 + k) * CCH;
        float4 v = *(const float4*)(src + c);
        v.x = __uint_as_float(f2tf(v.x)); v.y = __uint_as_float(f2tf(v.y));
        v.z = __uint_as_float(f2tf(v.z)); v.w = __uint_as_float(f2tf(v.w));
        *(float4*)(dst + c) = v;
    } else {
        *(float4*)(dst + c) = make_float4(0.f, 0.f, 0.f, 0.f);
    }
}

// ---------------- K2: attn_x ----------------
__global__ void k_attnx(const float* __restrict__ img) {
    int r = blockIdx.x; int b = r / NSP; int j = r - b * NSP;
    const float* x0 = img + (size_t)b * LVC * CCH;
    const float* xj = x0 + (size_t)(1 + j) * CCH;
    int tid = threadIdx.x;
    float d = 0.f;
    for (int c = tid; c < CCH; c += 128) d += x0[c] * xj[c];
    __shared__ float red[4];
    d = warpReduceSum(d);
    if ((tid & 31) == 0) red[tid >> 5] = d;
    __syncthreads();
    if (tid == 0) {
        float t = red[0]+red[1]+red[2]+red[3];
        g_attn_x[r] = t * g_inv_img[b * LVC] * g_inv_img[b * LVC + 1 + j];
    }
}

// ---------------- K3: cap_norm rows + gloT ----------------
__global__ void k_cap(const float* __restrict__ cap) {
    int r = blockIdx.x; int i = r / LTC; int t = r - i * LTC;
    const float* x = cap + (size_t)r * CCH;
    int tid = threadIdx.x;
    float ss = 0.f;
    for (int c = tid; c < CCH; c += 128) { float v = x[c]; ss += v * v; }
    __shared__ float red[4]; __shared__ float s_inv;
    ss = warpReduceSum(ss);
    if ((tid & 31) == 0) red[tid >> 5] = ss;
    __syncthreads();
    if (tid == 0) s_inv = 1.f / fmaxf(sqrtf(red[0]+red[1]+red[2]+red[3]), 1e-12f);
    __syncthreads();
    float inv = s_inv;
    float* dst = g_CAT + ((size_t)i * 96 + t) * CCH;
    for (int c = tid; c < CCH; c += 128) {
        float v = x[c] * inv;
        dst[c] = v;
        if (t == 0) g_gloT[c * NCAPC + i] = v;
    }
}

// ---------------- K4: CAT rows 32..95 = cap_norm @ W + b ----------------
__global__ __launch_bounds__(256) void k_capW(
    const float* __restrict__ wi2t, const float* __restrict__ bi2t,
    const float* __restrict__ wt2i, const float* __restrict__ bt2i) {
    extern __shared__ float s_xT[];     // [ci][34]
    int bx = blockIdx.x;
    int i = bx >> 2; int which = (bx >> 1) & 1; int halfid = bx & 1;
    int tid = threadIdx.x;
    int col = halfid * 256 + tid;
    const float* src = g_CAT + (size_t)i * 96 * CCH;
    for (int idx = tid; idx < LTC * CCH; idx += 256) {
        int t = idx >> 9; int c = idx & 511;
        s_xT[c * 34 + t] = src[idx];
    }
    __syncthreads();
    const float* W = which ? wt2i : wi2t;
    const float* bias = which ? bt2i : bi2t;
    ull acc[16];
    #pragma unroll
    for (int p = 0; p < 16; p++) acc[p] = 0ull;
    float w = W[col];
    for (int ci = 0; ci < CCH; ci++) {
        float wn = (ci < CCH - 1) ? W[(size_t)(ci + 1) * CCH + col] : 0.f;
        ull ww = pack2(w, w);
        const ull* xr = (const ull*)(s_xT + ci * 34);
        #pragma unroll
        for (int p = 0; p < 16; p++) fma2(acc[p], xr[p], ww);
        w = wn;
    }
    float bb = bias[col];
    float* dst = g_CAT + ((size_t)i * 96 + 32 + which * 32) * CCH;
    #pragma unroll
    for (int p = 0; p < 16; p++) {
        float2 f = unpack2(acc[p]);
        dst[(size_t)(2 * p) * CCH + col]     = f.x + bb;
        dst[(size_t)(2 * p + 1) * CCH + col] = f.y + bb;
    }
}

// ---------------- K5: W0, 16 tokens per block ----------------
__global__ __launch_bounds__(256) void k_W0(const float* __restrict__ img,
                     const float* __restrict__ gamma, const float* __restrict__ beta,
                     const float* __restrict__ w1, const float* __restrict__ b1,
                     const float* __restrict__ w2, const float* __restrict__ b2) {
    __shared__ float s_y[16 * CCH];
    __shared__ float s_h[16 * 104];
    int tid = threadIdx.x;
    int lane = tid & 31, wid = tid >> 5;
    int r0 = blockIdx.x * 16;
    #pragma unroll
    for (int rr = wid; rr < 16; rr += 8) {
        int tok = r0 + rr;
        int b = tok / NSP; int j = tok - b * NSP;
        const float* x = img + ((size_t)b * LVC + 1 + j) * CCH;
        float s = 0.f, ss = 0.f;
        for (int c = lane; c < CCH; c += 32) { float v = x[c]; s += v; ss += v * v; }
        s = warpReduceSum(s); ss = warpReduceSum(ss);
        float mean = s * (1.f / CCH);
        float var = ss * (1.f / CCH) - mean * mean;
        float rstd = 1.f / sqrtf(var + LN_EPSF);
        for (int c = lane; c < CCH; c += 32)
            s_y[rr * CCH + c] = (x[c] - mean) * rstd * gamma[c] + beta[c];
    }
    __syncthreads();
    for (int task = tid; task < 16 * HIDC; task += 256) {
        int row = task / HIDC; int col = task - row * HIDC;
        float acc = b1[col];
        const float* yr = s_y + row * CCH;
        #pragma unroll 8
        for (int c = 0; c < CCH; c++) acc += yr[c] * w1[(size_t)c * HIDC + col];
        s_h[row * 104 + col] = 0.5f * acc * (1.f + erff(acc * 0.70710678118654752f));
    }
    __syncthreads();
    for (int task = tid; task < 16 * KEEPEDC; task += 256) {
        int row = task / KEEPEDC; int col = task - row * KEEPEDC;
        float acc = b2[col];
        const float* hr = s_h + row * 104;
        #pragma unroll 6
        for (int c = 0; c < HIDC; c++) acc += hr[c] * w2[c * KEEPEDC + col];
        g_W0[(size_t)(r0 + row) * KEEPEDC + col] = acc;
    }
}

// ---------------- K6: attn_y tiled GEMM ----------------
__global__ __launch_bounds__(256) void k_attn_y(const float* __restrict__ img) {
    __shared__ float s_x[32 * 68];
    __shared__ float s_g[32 * 68];
    __shared__ int   s_off[64];
    __shared__ float s_inv[64];
    int tid = threadIdx.x;
    int r0 = blockIdx.x * 64;
    if (tid < 64) {
        int tok = r0 + tid;
        int b = tok / NSP; int j = tok - b * NSP;
        s_off[tid] = (b * LVC + 1 + j) * CCH;
        s_inv[tid] = g_inv_img[b * LVC + 1 + j];
    }
    __syncthreads();
    int tx = tid & 15, ty = tid >> 4;
    int i0 = tx * 4, t0 = ty * 4;
    float acc[4][4];
    #pragma unroll
    for (int a = 0; a < 4; a++)
        #pragma unroll
        for (int c = 0; c < 4; c++) acc[a][c] = 0.f;
    for (int c0 = 0; c0 < CCH; c0 += 32) {
        {
            int tk = tid >> 2; int cc0 = (tid & 3) * 8;
            const float* p = img + s_off[tk] + c0 + cc0;
            float4 v0 = *(const float4*)p;
            float4 v1 = *(const float4*)(p + 4);
            s_x[(cc0 + 0) * 68 + tk] = v0.x; s_x[(cc0 + 1) * 68 + tk] = v0.y;
            s_x[(cc0 + 2) * 68 + tk] = v0.z; s_x[(cc0 + 3) * 68 + tk] = v0.w;
            s_x[(cc0 + 4) * 68 + tk] = v1.x; s_x[(cc0 + 5) * 68 + tk] = v1.y;
            s_x[(cc0 + 6) * 68 + tk] = v1.z; s_x[(cc0 + 7) * 68 + tk] = v1.w;
        }
        {
            int cc = tid >> 3; int ii = (tid & 7) * 8;
            const float* p = g_gloT + (size_t)(c0 + cc) * NCAPC + ii;
            *(float4*)(s_g + cc * 68 + ii)     = *(const float4*)p;
            *(float4*)(s_g + cc * 68 + ii + 4) = *(const float4*)(p + 4);
        }
        __syncthreads();
        for (int cc = 0; cc < 32; cc++) {
            float4 gv = *(const float4*)(s_g + cc * 68 + i0);
            float4 xv = *(const float4*)(s_x + cc * 68 + t0);
            float xa[4] = {xv.x, xv.y, xv.z, xv.w};
            float gb[4] = {gv.x, gv.y, gv.z, gv.w};
            #pragma unroll
            for (int a = 0; a < 4; a++)
                #pragma unroll
                for (int c = 0; c < 4; c++) acc[a][c] += xa[a] * gb[c];
        }
        __syncthreads();
    }
    #pragma unroll
    for (int a = 0; a < 4; a++) {
        float inv = s_inv[t0 + a];
        #pragma unroll
        for (int c = 0; c < 4; c++)
            g_attn_y[(size_t)(i0 + c) * (BB * NSP) + r0 + t0 + a] = acc[a][c] * inv;
    }
}

// ---------------- K7: per-pair fused kernel (512 threads, MMA) ----------------
#define STT 57
#define OFF_STT 0
#define SZ_STT (512 * STT)                 // 29184
#define OFF_W   SZ_STT                     // [64][204] = 13056 (union w/ Ach)
#define OFF_ACH SZ_STT                     // [96][68] = 6528
#define OFF_U2  (SZ_STT + 13056)           // 42240: AC [98][52]=5096 / G [96][51]=4896
#define OFF_AC  OFF_U2
#define OFF_G   OFF_U2
#define OFF_WNON (OFF_U2 + 5096)           // 47336
#define OFF_SCORE (OFF_WNON + 98)          // 47434
#define OFF_ORDER (OFF_SCORE + 196)        // 47630
#define OFF_INVN  (OFF_ORDER + 196)        // 47826
#define OFF_CM (OFF_INVN + 56)
#define OFF_CZ (OFF_CM + 51)
#define OFF_RM (OFF_CZ + 51)
#define OFF_RZ (OFF_RM + 32)
#define OFF_RED (OFF_RZ + 32)
#define OFF_SCAL (OFF_RED + 16)
#define SMEM_FLOATS (OFF_SCAL + 8)         // 48072 floats = 192288 B

__global__ __launch_bounds__(512, 1) void k_pair(
    const float* __restrict__ img,
    const float* __restrict__ aggr_scale_p,
    const float* __restrict__ temp_p,
    float* __restrict__ out) {
    extern __shared__ float sm[];
    float* s_stT   = sm + OFF_STT;    // [c=512][l stride 57]
    float* s_W     = sm + OFF_W;      // [64][204]
    float* s_Ach   = sm + OFF_ACH;    // [96][68]
    float* s_AC    = sm + OFF_AC;     // [98][52]
    float* s_G     = sm + OFF_G;      // [96][51]
    float* s_wnon  = sm + OFF_WNON;
    float* s_score = sm + OFF_SCORE;
    int*   s_order = (int*)(sm + OFF_ORDER);
    float* s_invn  = sm + OFF_INVN;
    float* s_cm    = sm + OFF_CM;
    float* s_cz    = sm + OFF_CZ;
    float* s_rm    = sm + OFF_RM;
    float* s_rz    = sm + OFF_RZ;
    float* s_red   = sm + OFF_RED;
    float* s_scal  = sm + OFF_SCAL;

    int pair = blockIdx.x;
    int i = pair & (NCAPC - 1);
    int b = pair >> 6;
    int tid = threadIdx.x;
    int lane = tid & 31, wid = tid >> 5;
    int g = lane >> 2, t4 = lane & 3;

    // ---- 1. scores ----
    if (tid < NSP) {
        s_score[tid] = g_attn_x[b * NSP + tid]
                     + g_attn_y[(size_t)i * (BB * NSP) + b * NSP + tid];
    }
    __syncthreads();

    // ---- 2. stable rank ----
    if (tid < NSP) {
        float sj = s_score[tid];
        int rank = 0;
        for (int j2 = 0; j2 < NSP; j2++) {
            float s2 = s_score[j2];
            rank += (s2 > sj) || (s2 == sj && j2 < tid);
        }
        s_order[rank] = tid;
    }
    __syncthreads();

    // ---- 3a. softmax over nonkeep scores ----
    if (tid < 98) s_wnon[tid] = s_score[s_order[NKEEP + tid]];
    __syncthreads();
    if (wid == 0) {
        float m = -INFINITY;
        for (int t = lane; t < 98; t += 32) m = fmaxf(m, s_wnon[t]);
        m = warpReduceMax(m);
        if (lane == 0) s_scal[0] = m;
    }
    __syncthreads();
    if (tid < 98) s_wnon[tid] = expf(s_wnon[tid] - s_scal[0]);
    __syncthreads();
    if (wid == 0) {
        float z = 0.f;
        for (int t = lane; t < 98; t += 32) z += s_wnon[t];
        z = warpReduceSum(z);
        if (lane == 0) s_scal[1] = 1.f / z;
    }
    // ---- 3b. gather AC[jj][52] + zero W ----
    {
        float ascale = aggr_scale_p[0];
        for (int idx = tid; idx < NKEEP * KEEPEDC; idx += 512) {
            int jj = idx / KEEPEDC; int k = idx - jj * KEEPEDC;
            s_AC[jj * 52 + k] = g_W0[((size_t)b * NSP + s_order[jj]) * KEEPEDC + k] * ascale;
        }
        for (int idx = tid; idx < 64 * 204; idx += 512) s_W[idx] = 0.f;
    }
    __syncthreads();
    // ---- 3c. per-k softmax over 98 keep entries ----
    for (int k = wid; k < KEEPEDC; k += 16) {
        float km = -INFINITY;
        for (int jj = lane; jj < NKEEP; jj += 32) km = fmaxf(km, s_AC[jj * 52 + k]);
        km = warpReduceMax(km);
        float kz = 0.f;
        for (int jj = lane; jj < NKEEP; jj += 32) {
            float e = expf(s_AC[jj * 52 + k] - km);
            s_AC[jj * 52 + k] = e; kz += e;
        }
        kz = warpReduceSum(kz);
        float inv = 1.f / kz;
        for (int jj = lane; jj < NKEEP; jj += 32) s_AC[jj * 52 + k] *= inv;
    }
    __syncthreads();
    // ---- 3d. scatter into W (tf32), row 49 = wnon*invz, cls row into ST_T ----
    {
        for (int idx = tid; idx < NKEEP * KEEPEDC; idx += 512) {
            int jj = idx / KEEPEDC; int r = idx - jj * KEEPEDC;
            s_W[r * 204 + s_order[jj]] = __uint_as_float(f2tf(s_AC[jj * 52 + r]));
        }
        float invz = s_scal[1];
        if (tid < 98)
            s_W[49 * 204 + s_order[NKEEP + tid]] = __uint_as_float(f2tf(s_wnon[tid] * invz));
        s_stT[tid * STT + 0] = img[(size_t)b * LVC * CCH + tid];   // cls
    }
    __syncthreads();

    // ---- 4. MMA: D[64][512] = W[64][200] @ X[200][512], write ST_T[c][m+1] ----
    {
        int mg = wid & 1, ng = wid >> 1;
        int mb0 = mg * 32;
        const float* Bb = g_img32 + (size_t)b * 200 * CCH;
        for (int rr = 0; rr < 2; rr++) {
            int n0 = ng * 64 + rr * 32;
            float d[2][4][4];
            #pragma unroll
            for (int mt = 0; mt < 2; mt++)
                #pragma unroll
                for (int nt = 0; nt < 4; nt++)
                    #pragma unroll
                    for (int q = 0; q < 4; q++) d[mt][nt][q] = 0.f;
            for (int ks = 0; ks < 25; ks++) {
                int kk = ks * 8;
                unsigned a[2][4];
                #pragma unroll
                for (int mt = 0; mt < 2; mt++) {
                    const float* wp = s_W + (mb0 + mt * 16 + g) * 204 + kk + t4;
                    a[mt][0] = __float_as_uint(wp[0]);
                    a[mt][1] = __float_as_uint(wp[8 * 204]);
                    a[mt][2] = __float_as_uint(wp[4]);
                    a[mt][3] = __float_as_uint(wp[8 * 204 + 4]);
                }
                #pragma unroll
                for (int nt = 0; nt < 4; nt++) {
                    const float* bp = Bb + (size_t)(kk + t4) * CCH + n0 + nt * 8 + g;
                    unsigned b0 = __float_as_uint(bp[0]);
                    unsigned b1 = __float_as_uint(bp[4 * CCH]);
                    mma_tf32(d[0][nt], a[0][0], a[0][1], a[0][2], a[0][3], b0, b1);
                    mma_tf32(d[1][nt], a[1][0], a[1][1], a[1][2], a[1][3], b0, b1);
                }
            }
            #pragma unroll
            for (int mt = 0; mt < 2; mt++) {
                int mr = mb0 + mt * 16 + g;
                #pragma unroll
                for (int nt = 0; nt < 4; nt++) {
                    int nb = n0 + nt * 8 + t4 * 2;
                    if (mr + 1 < STT) {
                        s_stT[nb * STT + mr + 1]       = d[mt][nt][0];
                        s_stT[(nb + 1) * STT + mr + 1] = d[mt][nt][1];
                    }
                    if (mr + 9 < STT) {
                        s_stT[nb * STT + mr + 9]       = d[mt][nt][2];
                        s_stT[(nb + 1) * STT + mr + 9] = d[mt][nt][3];
                    }
                }
            }
        }
    }
    __syncthreads();

    // ---- 5. inverse norms of 51 sel_tok rows (read ST_T columns) ----
    for (int l = wid; l < 51; l += 16) {
        float ssq = 0.f;
        for (int c = lane; c < CCH; c += 32) { float v = s_stT[c * STT + l]; ssq += v * v; }
        ssq = warpReduceSum(ssq);
        if (lane == 0) s_invn[l] = 1.f / fmaxf(sqrtf(ssq), 1e-12f);
    }
    __syncthreads();

    // ---- 6. MMA: G[96][51] = CAT_i[96][512] @ ST_T (k-major), scaled by invn ----
    {
        bool act = (wid < 12);
        int mg = wid % 3, ng = wid / 3;
        int mb0 = mg * 32;
        int n0 = ng * 16;
        int ntiles = (ng == 3) ? 1 : 2;
        float d[2][2][4];
        #pragma unroll
        for (int mt = 0; mt < 2; mt++)
            #pragma unroll
            for (int nt = 0; nt < 2; nt++)
                #pragma unroll
                for (int q = 0; q < 4; q++) d[mt][nt][q] = 0.f;
        const float* E = g_CAT + (size_t)i * 96 * CCH;
        for (int ch = 0; ch < 8; ch++) {
            int kc = ch * 64;
            for (int q = tid; q < 96 * 16; q += 512) {
                int tt = q >> 4; int f4 = q & 15;
                float4 v = *(const float4*)(E + (size_t)tt * CCH + kc + f4 * 4);
                v.x = __uint_as_float(f2tf(v.x)); v.y = __uint_as_float(f2tf(v.y));
                v.z = __uint_as_float(f2tf(v.z)); v.w = __uint_as_float(f2tf(v.w));
                *(float4*)(s_Ach + tt * 68 + f4 * 4) = v;
            }
            __syncthreads();
            if (act) {
                for (int ks = 0; ks < 8; ks++) {
                    int kl = ks * 8;
                    unsigned a[2][4];
                    #pragma unroll
                    for (int mt = 0; mt < 2; mt++) {
                        const float* ap = s_Ach + (mb0 + mt * 16 + g) * 68 + kl + t4;
                        a[mt][0] = __float_as_uint(ap[0]);
                        a[mt][1] = __float_as_uint(ap[8 * 68]);
                        a[mt][2] = __float_as_uint(ap[4]);
                        a[mt][3] = __float_as_uint(ap[8 * 68 + 4]);
                    }
                    #pragma unroll
                    for (int nt = 0; nt < 2; nt++) {
                        if (nt < ntiles) {
                            const float* bp = s_stT + (size_t)(kc + kl + t4) * STT + n0 + nt * 8 + g;
                            unsigned b0 = f2tf(bp[0]);
                            unsigned b1 = f2tf(bp[4 * STT]);
                            mma_tf32(d[0][nt], a[0][0], a[0][1], a[0][2], a[0][3], b0, b1);
                            mma_tf32(d[1][nt], a[1][0], a[1][1], a[1][2], a[1][3], b0, b1);
                        }
                    }
                }
            }
            __syncthreads();
        }
        if (act) {
            #pragma unroll
            for (int mt = 0; mt < 2; mt++) {
                int tr = mb0 + mt * 16 + g;
                #pragma unroll
                for (int nt = 0; nt < 2; nt++) {
                    if (nt < ntiles) {
                        int l0 = n0 + nt * 8 + t4 * 2;
                        if (l0 < 51)     s_G[tr * 51 + l0]           = d[mt][nt][0] * s_invn[l0];
                        if (l0 + 1 < 51) s_G[tr * 51 + l0 + 1]       = d[mt][nt][1] * s_invn[l0 + 1];
                        if (l0 < 51)     s_G[(tr + 8) * 51 + l0]     = d[mt][nt][2] * s_invn[l0];
                        if (l0 + 1 < 51) s_G[(tr + 8) * 51 + l0 + 1] = d[mt][nt][3] * s_invn[l0 + 1];
                    }
                }
            }
        }
    }
    __syncthreads();

    // ---- 7. softmaxes + final reduction ----
    float invtemp = 1.f / temp_p[0];
    if (tid < 51) {
        int l = tid;
        float cm = -INFINITY;
        for (int t = 0; t < 32; t++) cm = fmaxf(cm, s_G[(32 + t) * 51 + l] * invtemp);
        float cz = 0.f;
        for (int t = 0; t < 32; t++) cz += expf(s_G[(32 + t) * 51 + l] * invtemp - cm);
        s_cm[l] = cm; s_cz[l] = cz;
    } else if (tid >= 64 && tid < 96) {
        int t = tid - 64;
        float rm = -INFINITY;
        for (int l = 0; l < 51; l++) rm = fmaxf(rm, s_G[(64 + t) * 51 + l] * invtemp);
        float rz = 0.f;
        for (int l = 0; l < 51; l++) rz += expf(s_G[(64 + t) * 51 + l] * invtemp - rm);
        s_rm[t] = rm; s_rz[t] = rz;
    }
    __syncthreads();
    float part = 0.f;
    for (int idx = tid; idx < 32 * 51; idx += 512) {
        int t = idx / 51; int l = idx - t * 51;
        float gg = s_G[t * 51 + l];
        float c2i = (gg >= 0.f) ? gg : 0.1f * gg;
        float li = s_G[(32 + t) * 51 + l] * invtemp;
        float lt = s_G[(64 + t) * 51 + l] * invtemp;
        float ai = expf(li - s_cm[l]) / s_cz[l];
        float at = expf(lt - s_rm[t]) / s_rz[t];
        part += c2i * (ai * (1.f / 51.f) + at * (1.f / 32.f));
    }
    part = warpReduceSum(part);
    if (lane == 0) s_red[wid] = part;
    __syncthreads();
    if (tid == 0) {
        float s = 0.f;
        for (int w = 0; w < 16; w++) s += s_red[w];
        out[b * NCAPC + i] = s;
    }
}

// ---------------- launch ----------------
extern "C" void kernel_launch(void* const* d_in, const int* in_sizes, int n_in,
                              void* d_out, int out_size) {
    const float* img    = (const float*)d_in[0];
    const float* cap    = (const float*)d_in[1];
    const float* gamma  = (const float*)d_in[3];
    const float* beta   = (const float*)d_in[4];
    const float* w1     = (const float*)d_in[5];
    const float* b1     = (const float*)d_in[6];
    const float* w2     = (const float*)d_in[7];
    const float* b2     = (const float*)d_in[8];
    const float* ascale = (const float*)d_in[9];
    const float* wi2t   = (const float*)d_in[10];
    const float* bi2t   = (const float*)d_in[11];
    const float* wt2i   = (const float*)d_in[12];
    const float* bt2i   = (const float*)d_in[13];
    const float* temp   = (const float*)d_in[14];
    float* out = (float*)d_out;

    cudaFuncSetAttribute(k_capW, cudaFuncAttributeMaxDynamicSharedMemorySize, 512 * 34 * 4);
    cudaFuncSetAttribute(k_pair, cudaFuncAttributeMaxDynamicSharedMemorySize, SMEM_FLOATS * 4);

    k_inv<<<BB * LVC, 128>>>(img);
    k_img32<<<BB * 200, 128>>>(img);
    k_cap<<<NCAPC * LTC, 128>>>(cap);
    k_attnx<<<BB * NSP, 128>>>(img);
    k_capW<<<NCAPC * 4, 256, 512 * 34 * 4>>>(wi2t, bi2t, wt2i, bt2i);
    k_W0<<<(BB * NSP) / 16, 256>>>(img, gamma, beta, w1, b1, w2, b2);
    k_attn_y<<<(BB * NSP) / 64, 256>>>(img);
    k_pair<<<NCAPC * BB, 512, SMEM_FLOATS * 4>>>(img, ascale, temp, out);
}

// round 13
// speedup vs baseline: 2.1967x; 1.5430x over previous
#include <cuda_runtime.h>
#include <cuda_fp16.h>
#include <math.h>

#define BB 64
#define NCAPC 64
#define LVC 197
#define NSP 196
#define LTC 32
#define CCH 512
#define NKEEP 98
#define KEEPEDC 49
#define HIDC 102
#define LN_EPSF 1e-5f

typedef unsigned long long ull;

__device__ float g_inv_img[BB * LVC];
__device__ float g_attn_x[BB * NSP];
__device__ float g_attn_y[(size_t)NCAPC * BB * NSP];     // [i][r]
__device__ float g_W0[(size_t)BB * NSP * KEEPEDC];
__device__ float g_CAT[(size_t)NCAPC * 96 * CCH];        // fp32 (rows 0..31 used as k_capW input)
__device__ __half g_CATh[(size_t)NCAPC * 96 * CCH];      // half [i][96][512]
__device__ float g_gloT[CCH * NCAPC];
__device__ __half g_imgTh[(size_t)BB * CCH * 208];       // half [b][c][k], k padded to 208 (>=196 zero)

__device__ __forceinline__ float warpReduceSum(float v) {
    #pragma unroll
    for (int o = 16; o > 0; o >>= 1) v += __shfl_xor_sync(0xffffffffu, v, o);
    return v;
}
__device__ __forceinline__ float warpReduceMax(float v) {
    #pragma unroll
    for (int o = 16; o > 0; o >>= 1) v = fmaxf(v, __shfl_xor_sync(0xffffffffu, v, o));
    return v;
}
__device__ __forceinline__ void fma2(ull& acc, ull a, ull b) {
    asm("fma.rn.f32x2 %0, %1, %2, %0;" : "+l"(acc) : "l"(a), "l"(b));
}
__device__ __forceinline__ ull pack2(float a, float b) {
    ull r; asm("mov.b64 %0, {%1, %2};" : "=l"(r) : "f"(a), "f"(b)); return r;
}
__device__ __forceinline__ float2 unpack2(ull v) {
    float2 f; asm("mov.b64 {%0, %1}, %2;" : "=f"(f.x), "=f"(f.y) : "l"(v)); return f;
}
__device__ __forceinline__ void mma_f16(float* d, unsigned a0, unsigned a1, unsigned a2, unsigned a3,
                                        unsigned b0, unsigned b1) {
    asm volatile("mma.sync.aligned.m16n8k16.row.col.f32.f16.f16.f32 "
                 "{%0,%1,%2,%3}, {%4,%5,%6,%7}, {%8,%9}, {%0,%1,%2,%3};"
                 : "+f"(d[0]), "+f"(d[1]), "+f"(d[2]), "+f"(d[3])
                 : "r"(a0), "r"(a1), "r"(a2), "r"(a3), "r"(b0), "r"(b1));
}

// ---------------- K1: inverse norms ----------------
__global__ void k_inv(const float* __restrict__ img) {
    int r = blockIdx.x;
    const float* x = img + (size_t)r * CCH;
    int tid = threadIdx.x;
    float ss = 0.f;
    for (int c = tid; c < CCH; c += 128) { float v = x[c]; ss += v * v; }
    __shared__ float red[4];
    ss = warpReduceSum(ss);
    if ((tid & 31) == 0) red[tid >> 5] = ss;
    __syncthreads();
    if (tid == 0) g_inv_img[r] = 1.f / fmaxf(sqrtf(red[0]+red[1]+red[2]+red[3]), 1e-12f);
}

// ---------------- K1b: img_sp -> half channel-major [b][512][208] ----------------
__global__ __launch_bounds__(512) void k_imgT(const float* __restrict__ img) {
    __shared__ float s[16 * 516];
    int b = blockIdx.x / 13, kt = blockIdx.x % 13;
    int k0 = kt * 16;
    int tid = threadIdx.x;
    for (int idx = tid; idx < 16 * 512; idx += 512) {
        int r = idx >> 9, c = idx & 511;
        int k = k0 + r;
        s[r * 516 + c] = (k < NSP) ? img[((size_t)b * LVC + 1 + k) * CCH + c] : 0.f;
    }
    __syncthreads();
    int c0 = tid >> 3, q = tid & 7;
    for (int it = 0; it < 8; it++) {
        int c = c0 + it * 64;
        __half2 h = __floats2half2_rn(s[(2 * q) * 516 + c], s[(2 * q + 1) * 516 + c]);
        *(__half2*)(g_imgTh + ((size_t)b * CCH + c) * 208 + k0 + 2 * q) = h;
    }
}

// ---------------- K2: attn_x ----------------
__global__ void k_attnx(const float* __restrict__ img) {
    int r = blockIdx.x; int b = r / NSP; int j = r - b * NSP;
    const float* x0 = img + (size_t)b * LVC * CCH;
    const float* xj = x0 + (size_t)(1 + j) * CCH;
    int tid = threadIdx.x;
    float d = 0.f;
    for (int c = tid; c < CCH; c += 128) d += x0[c] * xj[c];
    __shared__ float red[4];
    d = warpReduceSum(d);
    if ((tid & 31) == 0) red[tid >> 5] = d;
    __syncthreads();
    if (tid == 0) {
        float t = red[0]+red[1]+red[2]+red[3];
        g_attn_x[r] = t * g_inv_img[b * LVC] * g_inv_img[b * LVC + 1 + j];
    }
}

// ---------------- K3: cap_norm rows (fp32 + half) + gloT ----------------
__global__ void k_cap(const float* __restrict__ cap) {
    int r = blockIdx.x; int i = r / LTC; int t = r - i * LTC;
    const float* x = cap + (size_t)r * CCH;
    int tid = threadIdx.x;
    float ss = 0.f;
    for (int c = tid; c < CCH; c += 128) { float v = x[c]; ss += v * v; }
    __shared__ float red[4]; __shared__ float s_inv;
    ss = warpReduceSum(ss);
    if ((tid & 31) == 0) red[tid >> 5] = ss;
    __syncthreads();
    if (tid == 0) s_inv = 1.f / fmaxf(sqrtf(red[0]+red[1]+red[2]+red[3]), 1e-12f);
    __syncthreads();
    float inv = s_inv;
    float* dst = g_CAT + ((size_t)i * 96 + t) * CCH;
    __half* dsth = g_CATh + ((size_t)i * 96 + t) * CCH;
    for (int c = tid; c < CCH; c += 128) {
        float v = x[c] * inv;
        dst[c] = v;
        dsth[c] = __float2half(v);
        if (t == 0) g_gloT[c * NCAPC + i] = v;
    }
}

// ---------------- K4: CATh rows 32..95 = cap_norm @ W + b (half out) ----------------
__global__ __launch_bounds__(256) void k_capW(
    const float* __restrict__ wi2t, const float* __restrict__ bi2t,
    const float* __restrict__ wt2i, const float* __restrict__ bt2i) {
    extern __shared__ float s_xT[];     // [ci][34]
    int bx = blockIdx.x;
    int i = bx >> 2; int which = (bx >> 1) & 1; int halfid = bx & 1;
    int tid = threadIdx.x;
    int col = halfid * 256 + tid;
    const float* src = g_CAT + (size_t)i * 96 * CCH;
    for (int idx = tid; idx < LTC * CCH; idx += 256) {
        int t = idx >> 9; int c = idx & 511;
        s_xT[c * 34 + t] = src[idx];
    }
    __syncthreads();
    const float* W = which ? wt2i : wi2t;
    const float* bias = which ? bt2i : bi2t;
    ull acc[16];
    #pragma unroll
    for (int p = 0; p < 16; p++) acc[p] = 0ull;
    float w = W[col];
    for (int ci = 0; ci < CCH; ci++) {
        float wn = (ci < CCH - 1) ? W[(size_t)(ci + 1) * CCH + col] : 0.f;
        ull ww = pack2(w, w);
        const ull* xr = (const ull*)(s_xT + ci * 34);
        #pragma unroll
        for (int p = 0; p < 16; p++) fma2(acc[p], xr[p], ww);
        w = wn;
    }
    float bb = bias[col];
    __half* dst = g_CATh + ((size_t)i * 96 + 32 + which * 32) * CCH;
    #pragma unroll
    for (int p = 0; p < 16; p++) {
        float2 f = unpack2(acc[p]);
        dst[(size_t)(2 * p) * CCH + col]     = __float2half(f.x + bb);
        dst[(size_t)(2 * p + 1) * CCH + col] = __float2half(f.y + bb);
    }
}

// ---------------- K5: W0, 16 tokens per block ----------------
__global__ __launch_bounds__(256) void k_W0(const float* __restrict__ img,
                     const float* __restrict__ gamma, const float* __restrict__ beta,
                     const float* __restrict__ w1, const float* __restrict__ b1,
                     const float* __restrict__ w2, const float* __restrict__ b2) {
    __shared__ float s_y[16 * CCH];
    __shared__ float s_h[16 * 104];
    int tid = threadIdx.x;
    int lane = tid & 31, wid = tid >> 5;
    int r0 = blockIdx.x * 16;
    #pragma unroll
    for (int rr = wid; rr < 16; rr += 8) {
        int tok = r0 + rr;
        int b = tok / NSP; int j = tok - b * NSP;
        const float* x = img + ((size_t)b * LVC + 1 + j) * CCH;
        float s = 0.f, ss = 0.f;
        for (int c = lane; c < CCH; c += 32) { float v = x[c]; s += v; ss += v * v; }
        s = warpReduceSum(s); ss = warpReduceSum(ss);
        float mean = s * (1.f / CCH);
        float var = ss * (1.f / CCH) - mean * mean;
        float rstd = 1.f / sqrtf(var + LN_EPSF);
        for (int c = lane; c < CCH; c += 32)
            s_y[rr * CCH + c] = (x[c] - mean) * rstd * gamma[c] + beta[c];
    }
    __syncthreads();
    for (int task = tid; task < 16 * HIDC; task += 256) {
        int row = task / HIDC; int col = task - row * HIDC;
        float acc = b1[col];
        const float* yr = s_y + row * CCH;
        #pragma unroll 8
        for (int c = 0; c < CCH; c++) acc += yr[c] * w1[(size_t)c * HIDC + col];
        s_h[row * 104 + col] = 0.5f * acc * (1.f + erff(acc * 0.70710678118654752f));
    }
    __syncthreads();
    for (int task = tid; task < 16 * KEEPEDC; task += 256) {
        int row = task / KEEPEDC; int col = task - row * KEEPEDC;
        float acc = b2[col];
        const float* hr = s_h + row * 104;
        #pragma unroll 6
        for (int c = 0; c < HIDC; c++) acc += hr[c] * w2[c * KEEPEDC + col];
        g_W0[(size_t)(r0 + row) * KEEPEDC + col] = acc;
    }
}

// ---------------- K6: attn_y tiled GEMM ----------------
__global__ __launch_bounds__(256) void k_attn_y(const float* __restrict__ img) {
    __shared__ float s_x[32 * 68];
    __shared__ float s_g[32 * 68];
    __shared__ int   s_off[64];
    __shared__ float s_inv[64];
    int tid = threadIdx.x;
    int r0 = blockIdx.x * 64;
    if (tid < 64) {
        int tok = r0 + tid;
        int b = tok / NSP; int j = tok - b * NSP;
        s_off[tid] = (b * LVC + 1 + j) * CCH;
        s_inv[tid] = g_inv_img[b * LVC + 1 + j];
    }
    __syncthreads();
    int tx = tid & 15, ty = tid >> 4;
    int i0 = tx * 4, t0 = ty * 4;
    float acc[4][4];
    #pragma unroll
    for (int a = 0; a < 4; a++)
        #pragma unroll
        for (int c = 0; c < 4; c++) acc[a][c] = 0.f;
    for (int c0 = 0; c0 < CCH; c0 += 32) {
        {
            int tk = tid >> 2; int cc0 = (tid & 3) * 8;
            const float* p = img + s_off[tk] + c0 + cc0;
            float4 v0 = *(const float4*)p;
            float4 v1 = *(const float4*)(p + 4);
            s_x[(cc0 + 0) * 68 + tk] = v0.x; s_x[(cc0 + 1) * 68 + tk] = v0.y;
            s_x[(cc0 + 2) * 68 + tk] = v0.z; s_x[(cc0 + 3) * 68 + tk] = v0.w;
            s_x[(cc0 + 4) * 68 + tk] = v1.x; s_x[(cc0 + 5) * 68 + tk] = v1.y;
            s_x[(cc0 + 6) * 68 + tk] = v1.z; s_x[(cc0 + 7) * 68 + tk] = v1.w;
        }
        {
            int cc = tid >> 3; int ii = (tid & 7) * 8;
            const float* p = g_gloT + (size_t)(c0 + cc) * NCAPC + ii;
            *(float4*)(s_g + cc * 68 + ii)     = *(const float4*)p;
            *(float4*)(s_g + cc * 68 + ii + 4) = *(const float4*)(p + 4);
        }
        __syncthreads();
        for (int cc = 0; cc < 32; cc++) {
            float4 gv = *(const float4*)(s_g + cc * 68 + i0);
            float4 xv = *(const float4*)(s_x + cc * 68 + t0);
            float xa[4] = {xv.x, xv.y, xv.z, xv.w};
            float gb[4] = {gv.x, gv.y, gv.z, gv.w};
            #pragma unroll
            for (int a = 0; a < 4; a++)
                #pragma unroll
                for (int c = 0; c < 4; c++) acc[a][c] += xa[a] * gb[c];
        }
        __syncthreads();
    }
    #pragma unroll
    for (int a = 0; a < 4; a++) {
        float inv = s_inv[t0 + a];
        #pragma unroll
        for (int c = 0; c < 4; c++)
            g_attn_y[(size_t)(i0 + c) * (BB * NSP) + r0 + t0 + a] = acc[a][c] * inv;
    }
}

// ---------------- K7: per-pair fused kernel (512 threads, fp16 MMA, occ 2) ----------------
// smem (floats): STH [51][520]h=13260 | WH [64][216]h=6912 (G [96][51]=4896 unions here)
//                AC [98][52]=5096 (Ech [96][72]h=3456 unions here) | scalars
#define OFF_STH 0
#define OFF_WH  13260
#define OFF_G   13260
#define OFF_AC  20172
#define OFF_ECH 20172
#define OFF_SCORE 25268
#define OFF_ORDER (OFF_SCORE + 196)
#define OFF_WNON  (OFF_ORDER + 196)
#define OFF_INVN  (OFF_WNON + 98)
#define OFF_CM (OFF_INVN + 56)
#define OFF_CZ (OFF_CM + 51)
#define OFF_RM (OFF_CZ + 51)
#define OFF_RZ (OFF_RM + 32)
#define OFF_RED (OFF_RZ + 32)
#define OFF_SCAL (OFF_RED + 16)
#define SMEM_FLOATS (OFF_SCAL + 8)         // 26004 floats = 104016 B -> 2 CTAs/SM

__global__ __launch_bounds__(512, 2) void k_pair(
    const float* __restrict__ img,
    const float* __restrict__ aggr_scale_p,
    const float* __restrict__ temp_p,
    float* __restrict__ out) {
    extern __shared__ float sm[];
    __half* s_sth  = (__half*)(sm + OFF_STH);   // [l][c] stride 520
    __half* s_Wh   = (__half*)(sm + OFF_WH);    // [m][k] stride 216
    __half* s_Ech  = (__half*)(sm + OFF_ECH);   // [t][kk] stride 72
    float* s_AC    = sm + OFF_AC;               // [98][52]
    float* s_G     = sm + OFF_G;                // [96][51]
    float* s_score = sm + OFF_SCORE;
    int*   s_order = (int*)(sm + OFF_ORDER);
    float* s_wnon  = sm + OFF_WNON;
    float* s_invn  = sm + OFF_INVN;
    float* s_cm    = sm + OFF_CM;
    float* s_cz    = sm + OFF_CZ;
    float* s_rm    = sm + OFF_RM;
    float* s_rz    = sm + OFF_RZ;
    float* s_red   = sm + OFF_RED;
    float* s_scal  = sm + OFF_SCAL;

    int pair = blockIdx.x;
    int i = pair & (NCAPC - 1);
    int b = pair >> 6;
    int tid = threadIdx.x;
    int lane = tid & 31, wid = tid >> 5;
    int g = lane >> 2, t4 = lane & 3;

    // ---- 1. scores ----
    if (tid < NSP) {
        s_score[tid] = g_attn_x[b * NSP + tid]
                     + g_attn_y[(size_t)i * (BB * NSP) + b * NSP + tid];
    }
    __syncthreads();

    // ---- 2. stable rank ----
    if (tid < NSP) {
        float sj = s_score[tid];
        int rank = 0;
        for (int j2 = 0; j2 < NSP; j2++) {
            float s2 = s_score[j2];
            rank += (s2 > sj) || (s2 == sj && j2 < tid);
        }
        s_order[rank] = tid;
    }
    __syncthreads();

    // ---- 3a. softmax over nonkeep scores ----
    if (tid < 98) s_wnon[tid] = s_score[s_order[NKEEP + tid]];
    __syncthreads();
    if (wid == 0) {
        float m = -INFINITY;
        for (int t = lane; t < 98; t += 32) m = fmaxf(m, s_wnon[t]);
        m = warpReduceMax(m);
        if (lane == 0) s_scal[0] = m;
    }
    __syncthreads();
    if (tid < 98) s_wnon[tid] = expf(s_wnon[tid] - s_scal[0]);
    __syncthreads();
    if (wid == 0) {
        float z = 0.f;
        for (int t = lane; t < 98; t += 32) z += s_wnon[t];
        z = warpReduceSum(z);
        if (lane == 0) s_scal[1] = 1.f / z;
    }
    // ---- 3b. gather AC + zero W ----
    {
        float ascale = aggr_scale_p[0];
        for (int idx = tid; idx < NKEEP * KEEPEDC; idx += 512) {
            int jj = idx / KEEPEDC; int k = idx - jj * KEEPEDC;
            s_AC[jj * 52 + k] = g_W0[((size_t)b * NSP + s_order[jj]) * KEEPEDC + k] * ascale;
        }
        for (int idx = tid; idx < 6912; idx += 512) sm[OFF_WH + idx] = 0.f;
    }
    __syncthreads();
    // ---- 3c. per-k softmax over 98 keep entries ----
    for (int k = wid; k < KEEPEDC; k += 16) {
        float km = -INFINITY;
        for (int jj = lane; jj < NKEEP; jj += 32) km = fmaxf(km, s_AC[jj * 52 + k]);
        km = warpReduceMax(km);
        float kz = 0.f;
        for (int jj = lane; jj < NKEEP; jj += 32) {
            float e = expf(s_AC[jj * 52 + k] - km);
            s_AC[jj * 52 + k] = e; kz += e;
        }
        kz = warpReduceSum(kz);
        float inv = 1.f / kz;
        for (int jj = lane; jj < NKEEP; jj += 32) s_AC[jj * 52 + k] *= inv;
    }
    __syncthreads();
    // ---- 3d. scatter W (half), row 49 = wnon*invz; cls row -> s_sth ----
    {
        for (int idx = tid; idx < NKEEP * KEEPEDC; idx += 512) {
            int jj = idx / KEEPEDC; int r = idx - jj * KEEPEDC;
            s_Wh[r * 216 + s_order[jj]] = __float2half(s_AC[jj * 52 + r]);
        }
        float invz = s_scal[1];
        if (tid < 98)
            s_Wh[49 * 216 + s_order[NKEEP + tid]] = __float2half(s_wnon[tid] * invz);
        s_sth[tid] = __float2half(img[(size_t)b * LVC * CCH + tid]);   // row 0 = cls
    }
    __syncthreads();

    // ---- 4. fp16 MMA: D[64][512] = W[64][208] @ X^T, write s_sth rows 1..50 ----
    {
        int mg = wid & 1, ng = wid >> 1;
        int mb0 = mg * 32;
        const __half* Bb = g_imgTh + (size_t)b * CCH * 208;
        for (int rr = 0; rr < 4; rr++) {
            int n0 = ng * 64 + rr * 16;
            float d[2][2][4];
            #pragma unroll
            for (int mt = 0; mt < 2; mt++)
                #pragma unroll
                for (int nt = 0; nt < 2; nt++)
                    #pragma unroll
                    for (int q = 0; q < 4; q++) d[mt][nt][q] = 0.f;
            for (int ks = 0; ks < 13; ks++) {
                int kk = ks * 16;
                unsigned a[2][4];
                #pragma unroll
                for (int mt = 0; mt < 2; mt++) {
                    const __half* wp = s_Wh + (mb0 + mt * 16 + g) * 216 + kk + 2 * t4;
                    a[mt][0] = *(const unsigned*)wp;
                    a[mt][1] = *(const unsigned*)(wp + 8 * 216);
                    a[mt][2] = *(const unsigned*)(wp + 8);
                    a[mt][3] = *(const unsigned*)(wp + 8 * 216 + 8);
                }
                #pragma unroll
                for (int nt = 0; nt < 2; nt++) {
                    const __half* bp = Bb + (size_t)(n0 + nt * 8 + g) * 208 + kk + 2 * t4;
                    unsigned b0 = *(const unsigned*)bp;
                    unsigned b1 = *(const unsigned*)(bp + 8);
                    mma_f16(d[0][nt], a[0][0], a[0][1], a[0][2], a[0][3], b0, b1);
                    mma_f16(d[1][nt], a[1][0], a[1][1], a[1][2], a[1][3], b0, b1);
                }
            }
            #pragma unroll
            for (int mt = 0; mt < 2; mt++) {
                int mr = mb0 + mt * 16 + g;
                #pragma unroll
                for (int nt = 0; nt < 2; nt++) {
                    int nb = n0 + nt * 8 + 2 * t4;
                    if (mr + 1 <= 50)
                        *(__half2*)(s_sth + (mr + 1) * 520 + nb) = __floats2half2_rn(d[mt][nt][0], d[mt][nt][1]);
                    if (mr + 9 <= 50)
                        *(__half2*)(s_sth + (mr + 9) * 520 + nb) = __floats2half2_rn(d[mt][nt][2], d[mt][nt][3]);
                }
            }
        }
    }
    __syncthreads();

    // ---- 5. inverse norms of 51 sel_tok rows ----
    for (int l = wid; l < 51; l += 16) {
        float ssq = 0.f;
        for (int c = lane; c < CCH; c += 32) {
            float v = __half2float(s_sth[l * 520 + c]); ssq += v * v;
        }
        ssq = warpReduceSum(ssq);
        if (lane == 0) s_invn[l] = 1.f / fmaxf(sqrtf(ssq), 1e-12f);
    }
    __syncthreads();

    // ---- 6. fp16 MMA: G[96][51] = CAT_i @ sel_tok^T, chunked A staging ----
    {
        bool act = (wid < 12);
        int mg = wid % 3, ng = wid / 3;       // ng valid 0..3 when act
        int mb0 = mg * 32;
        int n0 = ng * 16;
        int ntiles = (ng == 3) ? 1 : 2;
        float d[2][2][4];
        #pragma unroll
        for (int mt = 0; mt < 2; mt++)
            #pragma unroll
            for (int nt = 0; nt < 2; nt++)
                #pragma unroll
                for (int q = 0; q < 4; q++) d[mt][nt][q] = 0.f;
        const unsigned* Eu = (const unsigned*)(g_CATh + (size_t)i * 96 * CCH);  // half2 units, row stride 256
        for (int ch = 0; ch < 8; ch++) {
            int kc = ch * 64;
            __syncthreads();
            for (int q = tid; q < 96 * 32; q += 512) {
                int r = q >> 5, w = q & 31;
                ((unsigned*)s_Ech)[r * 36 + w] = Eu[r * 256 + (kc >> 1) + w];
            }
            __syncthreads();
            if (act) {
                for (int ks = 0; ks < 4; ks++) {
                    int kl = ks * 16;
                    unsigned a[2][4];
                    #pragma unroll
                    for (int mt = 0; mt < 2; mt++) {
                        const __half* ap = s_Ech + (mb0 + mt * 16 + g) * 72 + kl + 2 * t4;
                        a[mt][0] = *(const unsigned*)ap;
                        a[mt][1] = *(const unsigned*)(ap + 8 * 72);
                        a[mt][2] = *(const unsigned*)(ap + 8);
                        a[mt][3] = *(const unsigned*)(ap + 8 * 72 + 8);
                    }
                    #pragma unroll
                    for (int nt = 0; nt < 2; nt++) {
                        if (nt < ntiles) {
                            const __half* bp = s_sth + (size_t)(n0 + nt * 8 + g) * 520 + kc + kl + 2 * t4;
                            unsigned b0 = *(const unsigned*)bp;
                            unsigned b1 = *(const unsigned*)(bp + 8);
                            mma_f16(d[0][nt], a[0][0], a[0][1], a[0][2], a[0][3], b0, b1);
                            mma_f16(d[1][nt], a[1][0], a[1][1], a[1][2], a[1][3], b0, b1);
                        }
                    }
                }
            }
        }
        __syncthreads();
        if (act) {
            #pragma unroll
            for (int mt = 0; mt < 2; mt++) {
                int tr = mb0 + mt * 16 + g;
                #pragma unroll
                for (int nt = 0; nt < 2; nt++) {
                    if (nt < ntiles) {
                        int l0 = n0 + nt * 8 + 2 * t4;
                        if (l0 < 51)     s_G[tr * 51 + l0]           = d[mt][nt][0] * s_invn[l0];
                        if (l0 + 1 < 51) s_G[tr * 51 + l0 + 1]       = d[mt][nt][1] * s_invn[l0 + 1];
                        if (l0 < 51)     s_G[(tr + 8) * 51 + l0]     = d[mt][nt][2] * s_invn[l0];
                        if (l0 + 1 < 51) s_G[(tr + 8) * 51 + l0 + 1] = d[mt][nt][3] * s_invn[l0 + 1];
                    }
                }
            }
        }
    }
    __syncthreads();

    // ---- 7. softmaxes + final reduction ----
    float invtemp = 1.f / temp_p[0];
    if (tid < 51) {
        int l = tid;
        float cm = -INFINITY;
        for (int t = 0; t < 32; t++) cm = fmaxf(cm, s_G[(32 + t) * 51 + l] * invtemp);
        float cz = 0.f;
        for (int t = 0; t < 32; t++) cz += expf(s_G[(32 + t) * 51 + l] * invtemp - cm);
        s_cm[l] = cm; s_cz[l] = cz;
    } else if (tid >= 64 && tid < 96) {
        int t = tid - 64;
        float rm = -INFINITY;
        for (int l = 0; l < 51; l++) rm = fmaxf(rm, s_G[(64 + t) * 51 + l] * invtemp);
        float rz = 0.f;
        for (int l = 0; l < 51; l++) rz += expf(s_G[(64 + t) * 51 + l] * invtemp - rm);
        s_rm[t] = rm; s_rz[t] = rz;
    }
    __syncthreads();
    float part = 0.f;
    for (int idx = tid; idx < 32 * 51; idx += 512) {
        int t = idx / 51; int l = idx - t * 51;
        float gg = s_G[t * 51 + l];
        float c2i = (gg >= 0.f) ? gg : 0.1f * gg;
        float li = s_G[(32 + t) * 51 + l] * invtemp;
        float lt = s_G[(64 + t) * 51 + l] * invtemp;
        float ai = expf(li - s_cm[l]) / s_cz[l];
        float at = expf(lt - s_rm[t]) / s_rz[t];
        part += c2i * (ai * (1.f / 51.f) + at * (1.f / 32.f));
    }
    part = warpReduceSum(part);
    if (lane == 0) s_red[wid] = part;
    __syncthreads();
    if (tid == 0) {
        float s = 0.f;
        for (int w = 0; w < 16; w++) s += s_red[w];
        out[b * NCAPC + i] = s;
    }
}

// ---------------- launch ----------------
extern "C" void kernel_launch(void* const* d_in, const int* in_sizes, int n_in,
                              void* d_out, int out_size) {
    const float* img    = (const float*)d_in[0];
    const float* cap    = (const float*)d_in[1];
    const float* gamma  = (const float*)d_in[3];
    const float* beta   = (const float*)d_in[4];
    const float* w1     = (const float*)d_in[5];
    const float* b1     = (const float*)d_in[6];
    const float* w2     = (const float*)d_in[7];
    const float* b2     = (const float*)d_in[8];
    const float* ascale = (const float*)d_in[9];
    const float* wi2t   = (const float*)d_in[10];
    const float* bi2t   = (const float*)d_in[11];
    const float* wt2i   = (const float*)d_in[12];
    const float* bt2i   = (const float*)d_in[13];
    const float* temp   = (const float*)d_in[14];
    float* out = (float*)d_out;

    cudaFuncSetAttribute(k_capW, cudaFuncAttributeMaxDynamicSharedMemorySize, 512 * 34 * 4);
    cudaFuncSetAttribute(k_pair, cudaFuncAttributeMaxDynamicSharedMemorySize, SMEM_FLOATS * 4);

    k_inv<<<BB * LVC, 128>>>(img);
    k_imgT<<<BB * 13, 512>>>(img);
    k_cap<<<NCAPC * LTC, 128>>>(cap);
    k_attnx<<<BB * NSP, 128>>>(img);
    k_capW<<<NCAPC * 4, 256, 512 * 34 * 4>>>(wi2t, bi2t, wt2i, bt2i);
    k_W0<<<(BB * NSP) / 16, 256>>>(img, gamma, beta, w1, b1, w2, b2);
    k_attn_y<<<(BB * NSP) / 64, 256>>>(img);
    k_pair<<<NCAPC * BB, 512, SMEM_FLOATS * 4>>>(img, ascale, temp, out);
}

// round 14
// speedup vs baseline: 2.7323x; 1.2438x over previous
#include <cuda_runtime.h>
#include <cuda_fp16.h>
#include <math.h>

#define BB 64
#define NCAPC 64
#define LVC 197
#define NSP 196
#define LTC 32
#define CCH 512
#define NKEEP 98
#define KEEPEDC 49
#define HIDC 102
#define LN_EPSF 1e-5f

typedef unsigned long long ull;

__device__ float g_inv_img[BB * LVC];
__device__ float g_attn_x[BB * NSP];
__device__ float g_attn_y[(size_t)NCAPC * BB * NSP];     // [i][r]
__device__ float g_W0[(size_t)BB * NSP * KEEPEDC];
__device__ float g_CAT[(size_t)NCAPC * 96 * CCH];        // fp32 (rows 0..31, k_capW input)
__device__ __half g_CATh[(size_t)NCAPC * 96 * CCH];      // half [i][96][512]
__device__ float g_gloT[CCH * NCAPC];
__device__ uint2 g_imgF[(size_t)BB * 64 * 13 * 32];      // stage-4 B fragments
__device__ uint4 g_catF[(size_t)NCAPC * 6 * 32 * 32];    // stage-6 A fragments

__device__ __forceinline__ float warpReduceSum(float v) {
    #pragma unroll
    for (int o = 16; o > 0; o >>= 1) v += __shfl_xor_sync(0xffffffffu, v, o);
    return v;
}
__device__ __forceinline__ float warpReduceMax(float v) {
    #pragma unroll
    for (int o = 16; o > 0; o >>= 1) v = fmaxf(v, __shfl_xor_sync(0xffffffffu, v, o));
    return v;
}
__device__ __forceinline__ void fma2(ull& acc, ull a, ull b) {
    asm("fma.rn.f32x2 %0, %1, %2, %0;" : "+l"(acc) : "l"(a), "l"(b));
}
__device__ __forceinline__ ull pack2(float a, float b) {
    ull r; asm("mov.b64 %0, {%1, %2};" : "=l"(r) : "f"(a), "f"(b)); return r;
}
__device__ __forceinline__ float2 unpack2(ull v) {
    float2 f; asm("mov.b64 {%0, %1}, %2;" : "=f"(f.x), "=f"(f.y) : "l"(v)); return f;
}
__device__ __forceinline__ unsigned h2u(__half2 h) { return *(unsigned*)&h; }
__device__ __forceinline__ void mma_f16(float* d, unsigned a0, unsigned a1, unsigned a2, unsigned a3,
                                        unsigned b0, unsigned b1) {
    asm volatile("mma.sync.aligned.m16n8k16.row.col.f32.f16.f16.f32 "
                 "{%0,%1,%2,%3}, {%4,%5,%6,%7}, {%8,%9}, {%0,%1,%2,%3};"
                 : "+f"(d[0]), "+f"(d[1]), "+f"(d[2]), "+f"(d[3])
                 : "r"(a0), "r"(a1), "r"(a2), "r"(a3), "r"(b0), "r"(b1));
}

// ---------------- K1: inverse norms ----------------
__global__ void k_inv(const float* __restrict__ img) {
    int r = blockIdx.x;
    const float* x = img + (size_t)r * CCH;
    int tid = threadIdx.x;
    float ss = 0.f;
    for (int c = tid; c < CCH; c += 128) { float v = x[c]; ss += v * v; }
    __shared__ float red[4];
    ss = warpReduceSum(ss);
    if ((tid & 31) == 0) red[tid >> 5] = ss;
    __syncthreads();
    if (tid == 0) g_inv_img[r] = 1.f / fmaxf(sqrtf(red[0]+red[1]+red[2]+red[3]), 1e-12f);
}

// ---------------- K1b: img_sp -> stage-4 B fragments [b][n8][k16][lane]{2x half2} ----------------
__global__ __launch_bounds__(512) void k_imgF(const float* __restrict__ img) {
    __shared__ float s[16 * 516];
    int b = blockIdx.x / 13, k16 = blockIdx.x % 13;
    int k0 = k16 * 16;
    int tid = threadIdx.x;
    for (int idx = tid; idx < 16 * 512; idx += 512) {
        int r = idx >> 9, c = idx & 511;
        int k = k0 + r;
        s[r * 516 + c] = (k < NSP) ? img[((size_t)b * LVC + 1 + k) * CCH + c] : 0.f;
    }
    __syncthreads();
    for (int it = 0; it < 4; it++) {
        int item = it * 512 + tid;
        int n8 = item >> 5, lane = item & 31;
        int g = lane >> 2, t4 = lane & 3;
        int c = n8 * 8 + g;
        int kl = 2 * t4;
        uint2 v;
        v.x = h2u(__floats2half2_rn(s[kl * 516 + c],       s[(kl + 1) * 516 + c]));
        v.y = h2u(__floats2half2_rn(s[(kl + 8) * 516 + c], s[(kl + 9) * 516 + c]));
        g_imgF[(((size_t)b * 64 + n8) * 13 + k16) * 32 + lane] = v;
    }
}

// ---------------- K2: attn_x ----------------
__global__ void k_attnx(const float* __restrict__ img) {
    int r = blockIdx.x; int b = r / NSP; int j = r - b * NSP;
    const float* x0 = img + (size_t)b * LVC * CCH;
    const float* xj = x0 + (size_t)(1 + j) * CCH;
    int tid = threadIdx.x;
    float d = 0.f;
    for (int c = tid; c < CCH; c += 128) d += x0[c] * xj[c];
    __shared__ float red[4];
    d = warpReduceSum(d);
    if ((tid & 31) == 0) red[tid >> 5] = d;
    __syncthreads();
    if (tid == 0) {
        float t = red[0]+red[1]+red[2]+red[3];
        g_attn_x[r] = t * g_inv_img[b * LVC] * g_inv_img[b * LVC + 1 + j];
    }
}

// ---------------- K3: cap_norm rows (fp32 + half) + gloT ----------------
__global__ void k_cap(const float* __restrict__ cap) {
    int r = blockIdx.x; int i = r / LTC; int t = r - i * LTC;
    const float* x = cap + (size_t)r * CCH;
    int tid = threadIdx.x;
    float ss = 0.f;
    for (int c = tid; c < CCH; c += 128) { float v = x[c]; ss += v * v; }
    __shared__ float red[4]; __shared__ float s_inv;
    ss = warpReduceSum(ss);
    if ((tid & 31) == 0) red[tid >> 5] = ss;
    __syncthreads();
    if (tid == 0) s_inv = 1.f / fmaxf(sqrtf(red[0]+red[1]+red[2]+red[3]), 1e-12f);
    __syncthreads();
    float inv = s_inv;
    float* dst = g_CAT + ((size_t)i * 96 + t) * CCH;
    __half* dsth = g_CATh + ((size_t)i * 96 + t) * CCH;
    for (int c = tid; c < CCH; c += 128) {
        float v = x[c] * inv;
        dst[c] = v;
        dsth[c] = __float2half(v);
        if (t == 0) g_gloT[c * NCAPC + i] = v;
    }
}

// ---------------- K4: CATh rows 32..95 = cap_norm @ W + b (half out) ----------------
__global__ __launch_bounds__(256) void k_capW(
    const float* __restrict__ wi2t, const float* __restrict__ bi2t,
    const float* __restrict__ wt2i, const float* __restrict__ bt2i) {
    extern __shared__ float s_xT[];     // [ci][34]
    int bx = blockIdx.x;
    int i = bx >> 2; int which = (bx >> 1) & 1; int halfid = bx & 1;
    int tid = threadIdx.x;
    int col = halfid * 256 + tid;
    const float* src = g_CAT + (size_t)i * 96 * CCH;
    for (int idx = tid; idx < LTC * CCH; idx += 256) {
        int t = idx >> 9; int c = idx & 511;
        s_xT[c * 34 + t] = src[idx];
    }
    __syncthreads();
    const float* W = which ? wt2i : wi2t;
    const float* bias = which ? bt2i : bi2t;
    ull acc[16];
    #pragma unroll
    for (int p = 0; p < 16; p++) acc[p] = 0ull;
    float w = W[col];
    for (int ci = 0; ci < CCH; ci++) {
        float wn = (ci < CCH - 1) ? W[(size_t)(ci + 1) * CCH + col] : 0.f;
        ull ww = pack2(w, w);
        const ull* xr = (const ull*)(s_xT + ci * 34);
        #pragma unroll
        for (int p = 0; p < 16; p++) fma2(acc[p], xr[p], ww);
        w = wn;
    }
    float bb = bias[col];
    __half* dst = g_CATh + ((size_t)i * 96 + 32 + which * 32) * CCH;
    #pragma unroll
    for (int p = 0; p < 16; p++) {
        float2 f = unpack2(acc[p]);
        dst[(size_t)(2 * p) * CCH + col]     = __float2half(f.x + bb);
        dst[(size_t)(2 * p + 1) * CCH + col] = __float2half(f.y + bb);
    }
}

// ---------------- K4b: CATh -> stage-6 A fragments [i][m16][k16][lane]{uint4} ----------------
__global__ __launch_bounds__(512) void k_catF() {
    int i = blockIdx.x / 6, m16 = blockIdx.x % 6;
    const __half* E = g_CATh + (size_t)i * 96 * CCH;
    int tid = threadIdx.x;
    for (int it = 0; it < 2; it++) {
        int item = it * 512 + tid;
        int k16 = item >> 5, lane = item & 31;
        int g = lane >> 2, t4 = lane & 3;
        int m = m16 * 16 + g;
        int k = k16 * 16 + 2 * t4;
        uint4 v;
        v.x = *(const unsigned*)(E + (size_t)m * CCH + k);
        v.y = *(const unsigned*)(E + (size_t)(m + 8) * CCH + k);
        v.z = *(const unsigned*)(E + (size_t)m * CCH + k + 8);
        v.w = *(const unsigned*)(E + (size_t)(m + 8) * CCH + k + 8);
        g_catF[(((size_t)i * 6 + m16) * 32 + k16) * 32 + lane] = v;
    }
}

// ---------------- K5: W0, 16 tokens per block ----------------
__global__ __launch_bounds__(256) void k_W0(const float* __restrict__ img,
                     const float* __restrict__ gamma, const float* __restrict__ beta,
                     const float* __restrict__ w1, const float* __restrict__ b1,
                     const float* __restrict__ w2, const float* __restrict__ b2) {
    __shared__ float s_y[16 * CCH];
    __shared__ float s_h[16 * 104];
    int tid = threadIdx.x;
    int lane = tid & 31, wid = tid >> 5;
    int r0 = blockIdx.x * 16;
    #pragma unroll
    for (int rr = wid; rr < 16; rr += 8) {
        int tok = r0 + rr;
        int b = tok / NSP; int j = tok - b * NSP;
        const float* x = img + ((size_t)b * LVC + 1 + j) * CCH;
        float s = 0.f, ss = 0.f;
        for (int c = lane; c < CCH; c += 32) { float v = x[c]; s += v; ss += v * v; }
        s = warpReduceSum(s); ss = warpReduceSum(ss);
        float mean = s * (1.f / CCH);
        float var = ss * (1.f / CCH) - mean * mean;
        float rstd = 1.f / sqrtf(var + LN_EPSF);
        for (int c = lane; c < CCH; c += 32)
            s_y[rr * CCH + c] = (x[c] - mean) * rstd * gamma[c] + beta[c];
    }
    __syncthreads();
    for (int task = tid; task < 16 * HIDC; task += 256) {
        int row = task / HIDC; int col = task - row * HIDC;
        float acc = b1[col];
        const float* yr = s_y + row * CCH;
        #pragma unroll 8
        for (int c = 0; c < CCH; c++) acc += yr[c] * w1[(size_t)c * HIDC + col];
        s_h[row * 104 + col] = 0.5f * acc * (1.f + erff(acc * 0.70710678118654752f));
    }
    __syncthreads();
    for (int task = tid; task < 16 * KEEPEDC; task += 256) {
        int row = task / KEEPEDC; int col = task - row * KEEPEDC;
        float acc = b2[col];
        const float* hr = s_h + row * 104;
        #pragma unroll 6
        for (int c = 0; c < HIDC; c++) acc += hr[c] * w2[c * KEEPEDC + col];
        g_W0[(size_t)(r0 + row) * KEEPEDC + col] = acc;
    }
}

// ---------------- K6: attn_y tiled GEMM ----------------
__global__ __launch_bounds__(256) void k_attn_y(const float* __restrict__ img) {
    __shared__ float s_x[32 * 68];
    __shared__ float s_g[32 * 68];
    __shared__ int   s_off[64];
    __shared__ float s_inv[64];
    int tid = threadIdx.x;
    int r0 = blockIdx.x * 64;
    if (tid < 64) {
        int tok = r0 + tid;
        int b = tok / NSP; int j = tok - b * NSP;
        s_off[tid] = (b * LVC + 1 + j) * CCH;
        s_inv[tid] = g_inv_img[b * LVC + 1 + j];
    }
    __syncthreads();
    int tx = tid & 15, ty = tid >> 4;
    int i0 = tx * 4, t0 = ty * 4;
    float acc[4][4];
    #pragma unroll
    for (int a = 0; a < 4; a++)
        #pragma unroll
        for (int c = 0; c < 4; c++) acc[a][c] = 0.f;
    for (int c0 = 0; c0 < CCH; c0 += 32) {
        {
            int tk = tid >> 2; int cc0 = (tid & 3) * 8;
            const float* p = img + s_off[tk] + c0 + cc0;
            float4 v0 = *(const float4*)p;
            float4 v1 = *(const float4*)(p + 4);
            s_x[(cc0 + 0) * 68 + tk] = v0.x; s_x[(cc0 + 1) * 68 + tk] = v0.y;
            s_x[(cc0 + 2) * 68 + tk] = v0.z; s_x[(cc0 + 3) * 68 + tk] = v0.w;
            s_x[(cc0 + 4) * 68 + tk] = v1.x; s_x[(cc0 + 5) * 68 + tk] = v1.y;
            s_x[(cc0 + 6) * 68 + tk] = v1.z; s_x[(cc0 + 7) * 68 + tk] = v1.w;
        }
        {
            int cc = tid >> 3; int ii = (tid & 7) * 8;
            const float* p = g_gloT + (size_t)(c0 + cc) * NCAPC + ii;
            *(float4*)(s_g + cc * 68 + ii)     = *(const float4*)p;
            *(float4*)(s_g + cc * 68 + ii + 4) = *(const float4*)(p + 4);
        }
        __syncthreads();
        for (int cc = 0; cc < 32; cc++) {
            float4 gv = *(const float4*)(s_g + cc * 68 + i0);
            float4 xv = *(const float4*)(s_x + cc * 68 + t0);
            float xa[4] = {xv.x, xv.y, xv.z, xv.w};
            float gb[4] = {gv.x, gv.y, gv.z, gv.w};
            #pragma unroll
            for (int a = 0; a < 4; a++)
                #pragma unroll
                for (int c = 0; c < 4; c++) acc[a][c] += xa[a] * gb[c];
        }
        __syncthreads();
    }
    #pragma unroll
    for (int a = 0; a < 4; a++) {
        float inv = s_inv[t0 + a];
        #pragma unroll
        for (int c = 0; c < 4; c++)
            g_attn_y[(size_t)(i0 + c) * (BB * NSP) + r0 + t0 + a] = acc[a][c] * inv;
    }
}

// ---------------- K7: per-pair fused kernel (512 threads, fp16 MMA, occ 2) ----------------
#define OFF_STH 0
#define OFF_WH  13260
#define OFF_G   13260
#define OFF_AC  20172
#define OFF_SCORE 25268
#define OFF_ORDER (OFF_SCORE + 196)
#define OFF_WNON  (OFF_ORDER + 196)
#define OFF_INVN  (OFF_WNON + 98)
#define OFF_CM (OFF_INVN + 56)
#define OFF_CZ (OFF_CM + 51)
#define OFF_RM (OFF_CZ + 51)
#define OFF_RZ (OFF_RM + 32)
#define OFF_RED (OFF_RZ + 32)
#define OFF_SCAL (OFF_RED + 16)
#define SMEM_FLOATS (OFF_SCAL + 8)         // 26004 floats = 104016 B -> 2 CTAs/SM

__global__ __launch_bounds__(512, 2) void k_pair(
    const float* __restrict__ img,
    const float* __restrict__ aggr_scale_p,
    const float* __restrict__ temp_p,
    float* __restrict__ out) {
    extern __shared__ float sm[];
    __half* s_sth  = (__half*)(sm + OFF_STH);   // [l][c] stride 520
    __half* s_Wh   = (__half*)(sm + OFF_WH);    // [m][k] stride 216
    float* s_AC    = sm + OFF_AC;               // [98][52]
    float* s_G     = sm + OFF_G;                // [96][51] (unions WH)
    float* s_score = sm + OFF_SCORE;
    int*   s_order = (int*)(sm + OFF_ORDER);
    float* s_wnon  = sm + OFF_WNON;
    float* s_invn  = sm + OFF_INVN;
    float* s_cm    = sm + OFF_CM;
    float* s_cz    = sm + OFF_CZ;
    float* s_rm    = sm + OFF_RM;
    float* s_rz    = sm + OFF_RZ;
    float* s_red   = sm + OFF_RED;
    float* s_scal  = sm + OFF_SCAL;

    int pair = blockIdx.x;
    int i = pair & (NCAPC - 1);
    int b = pair >> 6;
    int tid = threadIdx.x;
    int lane = tid & 31, wid = tid >> 5;
    int g = lane >> 2, t4 = lane & 3;

    // ---- 1. scores ----
    if (tid < NSP) {
        s_score[tid] = g_attn_x[b * NSP + tid]
                     + g_attn_y[(size_t)i * (BB * NSP) + b * NSP + tid];
    }
    __syncthreads();

    // ---- 2. stable rank ----
    if (tid < NSP) {
        float sj = s_score[tid];
        int rank = 0;
        for (int j2 = 0; j2 < NSP; j2++) {
            float s2 = s_score[j2];
            rank += (s2 > sj) || (s2 == sj && j2 < tid);
        }
        s_order[rank] = tid;
    }
    __syncthreads();

    // ---- 3a. softmax over nonkeep scores ----
    if (tid < 98) s_wnon[tid] = s_score[s_order[NKEEP + tid]];
    __syncthreads();
    if (wid == 0) {
        float m = -INFINITY;
        for (int t = lane; t < 98; t += 32) m = fmaxf(m, s_wnon[t]);
        m = warpReduceMax(m);
        if (lane == 0) s_scal[0] = m;
    }
    __syncthreads();
    if (tid < 98) s_wnon[tid] = expf(s_wnon[tid] - s_scal[0]);
    __syncthreads();
    if (wid == 0) {
        float z = 0.f;
        for (int t = lane; t < 98; t += 32) z += s_wnon[t];
        z = warpReduceSum(z);
        if (lane == 0) s_scal[1] = 1.f / z;
    }
    // ---- 3b. gather AC + zero W ----
    {
        float ascale = aggr_scale_p[0];
        for (int idx = tid; idx < NKEEP * KEEPEDC; idx += 512) {
            int jj = idx / KEEPEDC; int k = idx - jj * KEEPEDC;
            s_AC[jj * 52 + k] = g_W0[((size_t)b * NSP + s_order[jj]) * KEEPEDC + k] * ascale;
        }
        for (int idx = tid; idx < 6912; idx += 512) sm[OFF_WH + idx] = 0.f;
    }
    __syncthreads();
    // ---- 3c. per-k softmax over 98 keep entries ----
    for (int k = wid; k < KEEPEDC; k += 16) {
        float km = -INFINITY;
        for (int jj = lane; jj < NKEEP; jj += 32) km = fmaxf(km, s_AC[jj * 52 + k]);
        km = warpReduceMax(km);
        float kz = 0.f;
        for (int jj = lane; jj < NKEEP; jj += 32) {
            float e = expf(s_AC[jj * 52 + k] - km);
            s_AC[jj * 52 + k] = e; kz += e;
        }
        kz = warpReduceSum(kz);
        float inv = 1.f / kz;
        for (int jj = lane; jj < NKEEP; jj += 32) s_AC[jj * 52 + k] *= inv;
    }
    __syncthreads();
    // ---- 3d. scatter W (half), row 49 = wnon*invz; cls row -> s_sth ----
    {
        for (int idx = tid; idx < NKEEP * KEEPEDC; idx += 512) {
            int jj = idx / KEEPEDC; int r = idx - jj * KEEPEDC;
            s_Wh[r * 216 + s_order[jj]] = __float2half(s_AC[jj * 52 + r]);
        }
        float invz = s_scal[1];
        if (tid < 98)
            s_Wh[49 * 216 + s_order[NKEEP + tid]] = __float2half(s_wnon[tid] * invz);
        s_sth[tid] = __float2half(img[(size_t)b * LVC * CCH + tid]);   // row 0 = cls
    }
    __syncthreads();

    // ---- 4. fp16 MMA: D[64][512] = W[64][208] @ X^T, fragment-major B from L2 ----
    {
        int mg = wid & 1, ng = wid >> 1;
        int mb0 = mg * 32;
        const uint2* Bf = g_imgF + (size_t)b * 64 * 13 * 32;
        for (int rr = 0; rr < 4; rr++) {
            int n0 = ng * 64 + rr * 16;
            float d[2][2][4];
            #pragma unroll
            for (int mt = 0; mt < 2; mt++)
                #pragma unroll
                for (int nt = 0; nt < 2; nt++)
                    #pragma unroll
                    for (int q = 0; q < 4; q++) d[mt][nt][q] = 0.f;
            for (int ks = 0; ks < 13; ks++) {
                int kk = ks * 16;
                unsigned a[2][4];
                #pragma unroll
                for (int mt = 0; mt < 2; mt++) {
                    const __half* wp = s_Wh + (mb0 + mt * 16 + g) * 216 + kk + 2 * t4;
                    a[mt][0] = *(const unsigned*)wp;
                    a[mt][1] = *(const unsigned*)(wp + 8 * 216);
                    a[mt][2] = *(const unsigned*)(wp + 8);
                    a[mt][3] = *(const unsigned*)(wp + 8 * 216 + 8);
                }
                #pragma unroll
                for (int nt = 0; nt < 2; nt++) {
                    int n8 = (n0 + nt * 8) >> 3;
                    uint2 v = Bf[((n8 * 13 + ks) << 5) + lane];
                    mma_f16(d[0][nt], a[0][0], a[0][1], a[0][2], a[0][3], v.x, v.y);
                    mma_f16(d[1][nt], a[1][0], a[1][1], a[1][2], a[1][3], v.x, v.y);
                }
            }
            #pragma unroll
            for (int mt = 0; mt < 2; mt++) {
                int mr = mb0 + mt * 16 + g;
                #pragma unroll
                for (int nt = 0; nt < 2; nt++) {
                    int nb = n0 + nt * 8 + 2 * t4;
                    if (mr + 1 <= 50)
                        *(__half2*)(s_sth + (mr + 1) * 520 + nb) = __floats2half2_rn(d[mt][nt][0], d[mt][nt][1]);
                    if (mr + 9 <= 50)
                        *(__half2*)(s_sth + (mr + 9) * 520 + nb) = __floats2half2_rn(d[mt][nt][2], d[mt][nt][3]);
                }
            }
        }
    }
    __syncthreads();

    // ---- 5. inverse norms of 51 sel_tok rows ----
    for (int l = wid; l < 51; l += 16) {
        float ssq = 0.f;
        for (int c = lane; c < CCH; c += 32) {
            float v = __half2float(s_sth[l * 520 + c]); ssq += v * v;
        }
        ssq = warpReduceSum(ssq);
        if (lane == 0) s_invn[l] = 1.f / fmaxf(sqrtf(ssq), 1e-12f);
    }
    __syncthreads();

    // ---- 6. fp16 MMA: G[96][51] = CAT_i @ sel_tok^T, fragment-major A from L2 ----
    {
        bool act = (wid < 12);
        int mg = wid % 3, ng = wid / 3;
        int mb0 = mg * 32;
        int n0 = ng * 16;
        int ntiles = (ng == 3) ? 1 : 2;
        float d[2][2][4];
        #pragma unroll
        for (int mt = 0; mt < 2; mt++)
            #pragma unroll
            for (int nt = 0; nt < 2; nt++)
                #pragma unroll
                for (int q = 0; q < 4; q++) d[mt][nt][q] = 0.f;
        if (act) {
            const uint4* Af = g_catF + (size_t)i * 6 * 32 * 32;
            for (int ks = 0; ks < 32; ks++) {
                uint4 a0 = Af[(((mg * 2 + 0) * 32 + ks) << 5) + lane];
                uint4 a1 = Af[(((mg * 2 + 1) * 32 + ks) << 5) + lane];
                int kg = ks * 16;
                #pragma unroll
                for (int nt = 0; nt < 2; nt++) {
                    if (nt < ntiles) {
                        const __half* bp = s_sth + (size_t)(n0 + nt * 8 + g) * 520 + kg + 2 * t4;
                        unsigned b0 = *(const unsigned*)bp;
                        unsigned b1 = *(const unsigned*)(bp + 8);
                        mma_f16(d[0][nt], a0.x, a0.y, a0.z, a0.w, b0, b1);
                        mma_f16(d[1][nt], a1.x, a1.y, a1.z, a1.w, b0, b1);
                    }
                }
            }
        }
        // WH region is dead (last read before the stage-4-end barrier) -> G writes are safe
        if (act) {
            #pragma unroll
            for (int mt = 0; mt < 2; mt++) {
                int tr = mb0 + mt * 16 + g;
                #pragma unroll
                for (int nt = 0; nt < 2; nt++) {
                    if (nt < ntiles) {
                        int l0 = n0 + nt * 8 + 2 * t4;
                        if (l0 < 51)     s_G[tr * 51 + l0]           = d[mt][nt][0] * s_invn[l0];
                        if (l0 + 1 < 51) s_G[tr * 51 + l0 + 1]       = d[mt][nt][1] * s_invn[l0 + 1];
                        if (l0 < 51)     s_G[(tr + 8) * 51 + l0]     = d[mt][nt][2] * s_invn[l0];
                        if (l0 + 1 < 51) s_G[(tr + 8) * 51 + l0 + 1] = d[mt][nt][3] * s_invn[l0 + 1];
                    }
                }
            }
        }
    }
    __syncthreads();

    // ---- 7. softmaxes + final reduction ----
    float invtemp = 1.f / temp_p[0];
    if (tid < 51) {
        int l = tid;
        float cm = -INFINITY;
        for (int t = 0; t < 32; t++) cm = fmaxf(cm, s_G[(32 + t) * 51 + l] * invtemp);
        float cz = 0.f;
        for (int t = 0; t < 32; t++) cz += expf(s_G[(32 + t) * 51 + l] * invtemp - cm);
        s_cm[l] = cm; s_cz[l] = cz;
    } else if (tid >= 64 && tid < 96) {
        int t = tid - 64;
        float rm = -INFINITY;
        for (int l = 0; l < 51; l++) rm = fmaxf(rm, s_G[(64 + t) * 51 + l] * invtemp);
        float rz = 0.f;
        for (int l = 0; l < 51; l++) rz += expf(s_G[(64 + t) * 51 + l] * invtemp - rm);
        s_rm[t] = rm; s_rz[t] = rz;
    }
    __syncthreads();
    float part = 0.f;
    for (int idx = tid; idx < 32 * 51; idx += 512) {
        int t = idx / 51; int l = idx - t * 51;
        float gg = s_G[t * 51 + l];
        float c2i = (gg >= 0.f) ? gg : 0.1f * gg;
        float li = s_G[(32 + t) * 51 + l] * invtemp;
        float lt = s_G[(64 + t) * 51 + l] * invtemp;
        float ai = expf(li - s_cm[l]) / s_cz[l];
        float at = expf(lt - s_rm[t]) / s_rz[t];
        part += c2i * (ai * (1.f / 51.f) + at * (1.f / 32.f));
    }
    part = warpReduceSum(part);
    if (lane == 0) s_red[wid] = part;
    __syncthreads();
    if (tid == 0) {
        float s = 0.f;
        for (int w = 0; w < 16; w++) s += s_red[w];
        out[b * NCAPC + i] = s;
    }
}

// ---------------- launch ----------------
extern "C" void kernel_launch(void* const* d_in, const int* in_sizes, int n_in,
                              void* d_out, int out_size) {
    const float* img    = (const float*)d_in[0];
    const float* cap    = (const float*)d_in[1];
    const float* gamma  = (const float*)d_in[3];
    const float* beta   = (const float*)d_in[4];
    const float* w1     = (const float*)d_in[5];
    const float* b1     = (const float*)d_in[6];
    const float* w2     = (const float*)d_in[7];
    const float* b2     = (const float*)d_in[8];
    const float* ascale = (const float*)d_in[9];
    const float* wi2t   = (const float*)d_in[10];
    const float* bi2t   = (const float*)d_in[11];
    const float* wt2i   = (const float*)d_in[12];
    const float* bt2i   = (const float*)d_in[13];
    const float* temp   = (const float*)d_in[14];
    float* out = (float*)d_out;

    cudaFuncSetAttribute(k_capW, cudaFuncAttributeMaxDynamicSharedMemorySize, 512 * 34 * 4);
    cudaFuncSetAttribute(k_pair, cudaFuncAttributeMaxDynamicSharedMemorySize, SMEM_FLOATS * 4);

    k_inv<<<BB * LVC, 128>>>(img);
    k_imgF<<<BB * 13, 512>>>(img);
    k_cap<<<NCAPC * LTC, 128>>>(cap);
    k_attnx<<<BB * NSP, 128>>>(img);
    k_capW<<<NCAPC * 4, 256, 512 * 34 * 4>>>(wi2t, bi2t, wt2i, bt2i);
    k_catF<<<NCAPC * 6, 512>>>();
    k_W0<<<(BB * NSP) / 16, 256>>>(img, gamma, beta, w1, b1, w2, b2);
    k_attn_y<<<(BB * NSP) / 64, 256>>>(img);
    k_pair<<<NCAPC * BB, 512, SMEM_FLOATS * 4>>>(img, ascale, temp, out);
}

// round 17
// speedup vs baseline: 3.9911x; 1.4607x over previous
#include <cuda_runtime.h>
#include <cuda_fp16.h>
#include <math.h>

#define BB 64
#define NCAPC 64
#define LVC 197
#define NSP 196
#define LTC 32
#define CCH 512
#define NKEEP 98
#define KEEPEDC 49
#define HIDC 102
#define LN_EPSF 1e-5f

typedef unsigned long long ull;

__device__ float g_inv_img[BB * LVC];
__device__ float g_attn_x[BB * NSP];
__device__ float g_attn_y[(size_t)NCAPC * BB * NSP];     // [i][r]
__device__ float g_W0[(size_t)BB * NSP * KEEPEDC];
__device__ __half g_CATh[(size_t)NCAPC * 96 * CCH];      // half [i][96][512]
__device__ float g_gloT[CCH * NCAPC];
__device__ uint2 g_imgF[(size_t)BB * 64 * 13 * 32];      // k_pair stage-4 B fragments
__device__ uint4 g_catF[(size_t)NCAPC * 6 * 32 * 32];    // k_pair stage-6 A fragments
__device__ uint2 g_w1F[13 * 32 * 32];                    // w1 B fragments  [n8][k16][lane]
__device__ uint2 g_w2F[7 * 7 * 32];                      // w2 B fragments
__device__ uint2 g_wF[2 * 64 * 32 * 32];                 // wi2t/wt2i B fragments [which][n8][k16][lane]

__device__ __forceinline__ float warpReduceSum(float v) {
    #pragma unroll
    for (int o = 16; o > 0; o >>= 1) v += __shfl_xor_sync(0xffffffffu, v, o);
    return v;
}
__device__ __forceinline__ float warpReduceMax(float v) {
    #pragma unroll
    for (int o = 16; o > 0; o >>= 1) v = fmaxf(v, __shfl_xor_sync(0xffffffffu, v, o));
    return v;
}
__device__ __forceinline__ unsigned h2u(__half2 h) { return *(unsigned*)&h; }
__device__ __forceinline__ void mma_f16(float* d, unsigned a0, unsigned a1, unsigned a2, unsigned a3,
                                        unsigned b0, unsigned b1) {
    asm volatile("mma.sync.aligned.m16n8k16.row.col.f32.f16.f16.f32 "
                 "{%0,%1,%2,%3}, {%4,%5,%6,%7}, {%8,%9}, {%0,%1,%2,%3};"
                 : "+f"(d[0]), "+f"(d[1]), "+f"(d[2]), "+f"(d[3])
                 : "r"(a0), "r"(a1), "r"(a2), "r"(a3), "r"(b0), "r"(b1));
}

// ---------------- K1: inverse norms ----------------
__global__ void k_inv(const float* __restrict__ img) {
    int r = blockIdx.x;
    const float* x = img + (size_t)r * CCH;
    int tid = threadIdx.x;
    float ss = 0.f;
    for (int c = tid; c < CCH; c += 128) { float v = x[c]; ss += v * v; }
    __shared__ float red[4];
    ss = warpReduceSum(ss);
    if ((tid & 31) == 0) red[tid >> 5] = ss;
    __syncthreads();
    if (tid == 0) g_inv_img[r] = 1.f / fmaxf(sqrtf(red[0]+red[1]+red[2]+red[3]), 1e-12f);
}

// ---------------- K1b: img_sp -> stage-4 B fragments ----------------
__global__ __launch_bounds__(512) void k_imgF(const float* __restrict__ img) {
    __shared__ float s[16 * 516];
    int b = blockIdx.x / 13, k16 = blockIdx.x % 13;
    int k0 = k16 * 16;
    int tid = threadIdx.x;
    for (int idx = tid; idx < 16 * 512; idx += 512) {
        int r = idx >> 9, c = idx & 511;
        int k = k0 + r;
        s[r * 516 + c] = (k < NSP) ? img[((size_t)b * LVC + 1 + k) * CCH + c] : 0.f;
    }
    __syncthreads();
    for (int it = 0; it < 4; it++) {
        int item = it * 512 + tid;
        int n8 = item >> 5, lane = item & 31;
        int g = lane >> 2, t4 = lane & 3;
        int c = n8 * 8 + g;
        int kl = 2 * t4;
        uint2 v;
        v.x = h2u(__floats2half2_rn(s[kl * 516 + c],       s[(kl + 1) * 516 + c]));
        v.y = h2u(__floats2half2_rn(s[(kl + 8) * 516 + c], s[(kl + 9) * 516 + c]));
        g_imgF[(((size_t)b * 64 + n8) * 13 + k16) * 32 + lane] = v;
    }
}

// ---------------- weight fragment packers ----------------
__global__ void k_w1F(const float* __restrict__ w1) {
    int idx = blockIdx.x * 256 + threadIdx.x;
    if (idx >= 13 * 32 * 32) return;
    int n8 = idx >> 10; int rem = idx & 1023;
    int k16 = rem >> 5; int lane = rem & 31;
    int g = lane >> 2, t4 = lane & 3;
    int n = n8 * 8 + g; int k0 = k16 * 16 + 2 * t4;
    float f0 = (n < HIDC) ? w1[(size_t)k0 * HIDC + n] : 0.f;
    float f1 = (n < HIDC) ? w1[(size_t)(k0 + 1) * HIDC + n] : 0.f;
    float f2 = (n < HIDC) ? w1[(size_t)(k0 + 8) * HIDC + n] : 0.f;
    float f3 = (n < HIDC) ? w1[(size_t)(k0 + 9) * HIDC + n] : 0.f;
    uint2 v; v.x = h2u(__floats2half2_rn(f0, f1)); v.y = h2u(__floats2half2_rn(f2, f3));
    g_w1F[idx] = v;
}
__global__ void k_w2F(const float* __restrict__ w2) {
    int idx = blockIdx.x * 256 + threadIdx.x;
    if (idx >= 7 * 7 * 32) return;
    int n8 = idx / (7 * 32); int rem = idx % (7 * 32);
    int k16 = rem >> 5; int lane = rem & 31;
    int g = lane >> 2, t4 = lane & 3;
    int n = n8 * 8 + g; int k0 = k16 * 16 + 2 * t4;
    float f0 = (n < KEEPEDC && k0     < HIDC) ? w2[(k0)     * KEEPEDC + n] : 0.f;
    float f1 = (n < KEEPEDC && k0 + 1 < HIDC) ? w2[(k0 + 1) * KEEPEDC + n] : 0.f;
    float f2 = (n < KEEPEDC && k0 + 8 < HIDC) ? w2[(k0 + 8) * KEEPEDC + n] : 0.f;
    float f3 = (n < KEEPEDC && k0 + 9 < HIDC) ? w2[(k0 + 9) * KEEPEDC + n] : 0.f;
    uint2 v; v.x = h2u(__floats2half2_rn(f0, f1)); v.y = h2u(__floats2half2_rn(f2, f3));
    g_w2F[idx] = v;
}
__global__ void k_wF(const float* __restrict__ wi2t, const float* __restrict__ wt2i) {
    int idx = blockIdx.x * 256 + threadIdx.x;
    int which = idx >> 16;                   // 64*32*32 = 65536 per matrix
    int rem = idx & 65535;
    int n8 = rem >> 10; int rem2 = rem & 1023;
    int k16 = rem2 >> 5; int lane = rem2 & 31;
    int g = lane >> 2, t4 = lane & 3;
    int n = n8 * 8 + g; int k0 = k16 * 16 + 2 * t4;
    const float* W = which ? wt2i : wi2t;
    uint2 v;
    v.x = h2u(__floats2half2_rn(W[(size_t)k0 * CCH + n],       W[(size_t)(k0 + 1) * CCH + n]));
    v.y = h2u(__floats2half2_rn(W[(size_t)(k0 + 8) * CCH + n], W[(size_t)(k0 + 9) * CCH + n]));
    g_wF[idx] = v;
}

// ---------------- K2: attn_x ----------------
__global__ void k_attnx(const float* __restrict__ img) {
    int r = blockIdx.x; int b = r / NSP; int j = r - b * NSP;
    const float* x0 = img + (size_t)b * LVC * CCH;
    const float* xj = x0 + (size_t)(1 + j) * CCH;
    int tid = threadIdx.x;
    float d = 0.f;
    for (int c = tid; c < CCH; c += 128) d += x0[c] * xj[c];
    __shared__ float red[4];
    d = warpReduceSum(d);
    if ((tid & 31) == 0) red[tid >> 5] = d;
    __syncthreads();
    if (tid == 0) {
        float t = red[0]+red[1]+red[2]+red[3];
        g_attn_x[r] = t * g_inv_img[b * LVC] * g_inv_img[b * LVC + 1 + j];
    }
}

// ---------------- K3: cap_norm rows (half) + gloT ----------------
__global__ void k_cap(const float* __restrict__ cap) {
    int r = blockIdx.x; int i = r / LTC; int t = r - i * LTC;
    const float* x = cap + (size_t)r * CCH;
    int tid = threadIdx.x;
    float ss = 0.f;
    for (int c = tid; c < CCH; c += 128) { float v = x[c]; ss += v * v; }
    __shared__ float red[4]; __shared__ float s_inv;
    ss = warpReduceSum(ss);
    if ((tid & 31) == 0) red[tid >> 5] = ss;
    __syncthreads();
    if (tid == 0) s_inv = 1.f / fmaxf(sqrtf(red[0]+red[1]+red[2]+red[3]), 1e-12f);
    __syncthreads();
    float inv = s_inv;
    __half* dsth = g_CATh + ((size_t)i * 96 + t) * CCH;
    for (int c = tid; c < CCH; c += 128) {
        float v = x[c] * inv;
        dsth[c] = __float2half(v);
        if (t == 0) g_gloT[c * NCAPC + i] = v;
    }
}

// ---------------- K4: CATh rows 32..95 via fp16 MMA ----------------
__global__ __launch_bounds__(512) void k_capW(
    const float* __restrict__ bi2t, const float* __restrict__ bt2i) {
    __shared__ __half s_ca[32 * 520];
    __shared__ float s_bi[2][512];
    int i = blockIdx.x;
    int tid = threadIdx.x;
    int lane = tid & 31, wid = tid >> 5;
    int g = lane >> 2, t4 = lane & 3;
    {
        const unsigned* src = (const unsigned*)(g_CATh + (size_t)i * 96 * CCH);
        for (int idx = tid; idx < 32 * 256; idx += 512) {
            int r = idx >> 8, w = idx & 255;
            ((unsigned*)s_ca)[r * 260 + w] = src[r * 256 + w];
        }
        if (tid < 512) { s_bi[0][tid] = bi2t[tid]; s_bi[1][tid] = bt2i[tid]; }
    }
    __syncthreads();
    int mg = wid & 1, ng = wid >> 1;
    int m0 = mg * 16;
    for (int which = 0; which < 2; which++) {
        float d[8][4];
        #pragma unroll
        for (int t = 0; t < 8; t++)
            #pragma unroll
            for (int q = 0; q < 4; q++) d[t][q] = 0.f;
        const uint2* Bf = g_wF + (size_t)which * 64 * 32 * 32;
        for (int ks = 0; ks < 32; ks++) {
            const __half* ap = s_ca + (m0 + g) * 520 + ks * 16 + 2 * t4;
            unsigned a0 = *(const unsigned*)ap;
            unsigned a1 = *(const unsigned*)(ap + 8 * 520);
            unsigned a2 = *(const unsigned*)(ap + 8);
            unsigned a3 = *(const unsigned*)(ap + 8 * 520 + 8);
            #pragma unroll
            for (int t = 0; t < 8; t++) {
                int n8 = ng * 8 + t;
                uint2 v = Bf[((n8 * 32 + ks) << 5) + lane];
                mma_f16(d[t], a0, a1, a2, a3, v.x, v.y);
            }
        }
        __half* dst = g_CATh + ((size_t)i * 96 + 32 + which * 32) * CCH;
        #pragma unroll
        for (int t = 0; t < 8; t++) {
            int col = (ng * 8 + t) * 8 + 2 * t4;
            int m = m0 + g;
            *(__half2*)(dst + (size_t)m * CCH + col) =
                __floats2half2_rn(d[t][0] + s_bi[which][col], d[t][1] + s_bi[which][col + 1]);
            *(__half2*)(dst + (size_t)(m + 8) * CCH + col) =
                __floats2half2_rn(d[t][2] + s_bi[which][col], d[t][3] + s_bi[which][col + 1]);
        }
    }
}

// ---------------- K4b: CATh -> stage-6 A fragments ----------------
__global__ __launch_bounds__(512) void k_catF() {
    int i = blockIdx.x / 6, m16 = blockIdx.x % 6;
    const __half* E = g_CATh + (size_t)i * 96 * CCH;
    int tid = threadIdx.x;
    for (int it = 0; it < 2; it++) {
        int item = it * 512 + tid;
        int k16 = item >> 5, lane = item & 31;
        int g = lane >> 2, t4 = lane & 3;
        int m = m16 * 16 + g;
        int k = k16 * 16 + 2 * t4;
        uint4 v;
        v.x = *(const unsigned*)(E + (size_t)m * CCH + k);
        v.y = *(const unsigned*)(E + (size_t)(m + 8) * CCH + k);
        v.z = *(const unsigned*)(E + (size_t)m * CCH + k + 8);
        v.w = *(const unsigned*)(E + (size_t)(m + 8) * CCH + k + 8);
        g_catF[(((size_t)i * 6 + m16) * 32 + k16) * 32 + lane] = v;
    }
}

// ---------------- K5: W0 via fp16 MMA, 64 tokens per block ----------------
#define W0_LN 0
#define W0_H  16640
#define W0_B1 20480
#define W0_B2 20584
#define W0_SMEM 20640                       // floats = 82560 B

__global__ __launch_bounds__(512, 2) void k_W0(const float* __restrict__ img,
                     const float* __restrict__ gamma, const float* __restrict__ beta,
                     const float* __restrict__ b1, const float* __restrict__ b2) {
    extern __shared__ float sw[];
    __half* s_ln = (__half*)(sw + W0_LN);   // [64][520]
    __half* s_h  = (__half*)(sw + W0_H);    // [64][120]
    float* s_b1  = sw + W0_B1;              // 104
    float* s_b2  = sw + W0_B2;              // 56
    int tid = threadIdx.x;
    int lane = tid & 31, wid = tid >> 5;
    int g = lane >> 2, t4 = lane & 3;
    int r0 = blockIdx.x * 64;

    for (int idx = tid; idx < 64 * 60; idx += 512) ((unsigned*)s_h)[idx] = 0u;
    if (tid < 104) s_b1[tid] = (tid < HIDC) ? b1[tid] : 0.f;
    if (tid >= 104 && tid < 160) s_b2[tid - 104] = (tid - 104 < KEEPEDC) ? b2[tid - 104] : 0.f;

    // LN: warp wid handles rows wid*4 .. wid*4+3
    for (int q = 0; q < 4; q++) {
        int row = wid * 4 + q;
        int tok = r0 + row;
        int b = tok / NSP; int j = tok - b * NSP;
        const float* x = img + ((size_t)b * LVC + 1 + j) * CCH;
        float xv[16];
        float s = 0.f, ss = 0.f;
        #pragma unroll
        for (int t = 0; t < 16; t++) {
            xv[t] = x[lane + t * 32];
            s += xv[t]; ss += xv[t] * xv[t];
        }
        s = warpReduceSum(s); ss = warpReduceSum(ss);
        float mean = s * (1.f / CCH);
        float var = ss * (1.f / CCH) - mean * mean;
        float rstd = 1.f / sqrtf(var + LN_EPSF);
        #pragma unroll
        for (int t = 0; t < 16; t++) {
            int c = lane + t * 32;
            s_ln[row * 520 + c] = __float2half((xv[t] - mean) * rstd * gamma[c] + beta[c]);
        }
    }
    __syncthreads();

    // MMA1: h[64][104] = ln[64][512] @ w1, gelu
    {
        int mg = wid & 3, ng = wid >> 2;
        int m0 = mg * 16;
        float d[4][4];
        #pragma unroll
        for (int t = 0; t < 4; t++)
            #pragma unroll
            for (int q = 0; q < 4; q++) d[t][q] = 0.f;
        for (int ks = 0; ks < 32; ks++) {
            const __half* ap = s_ln + (m0 + g) * 520 + ks * 16 + 2 * t4;
            unsigned a0 = *(const unsigned*)ap;
            unsigned a1 = *(const unsigned*)(ap + 8 * 520);
            unsigned a2 = *(const unsigned*)(ap + 8);
            unsigned a3 = *(const unsigned*)(ap + 8 * 520 + 8);
            #pragma unroll
            for (int t = 0; t < 4; t++) {
                int n8 = ng * 4 + t;
                if (n8 < 13) {
                    uint2 v = g_w1F[((n8 * 32 + ks) << 5) + lane];
                    mma_f16(d[t], a0, a1, a2, a3, v.x, v.y);
                }
            }
        }
        #pragma unroll
        for (int t = 0; t < 4; t++) {
            int n8 = ng * 4 + t;
            if (n8 < 13) {
                int col = n8 * 8 + 2 * t4;
                float v0 = d[t][0] + s_b1[col], v1 = d[t][1] + s_b1[col + 1];
                float v2 = d[t][2] + s_b1[col], v3 = d[t][3] + s_b1[col + 1];
                v0 = 0.5f * v0 * (1.f + erff(v0 * 0.70710678118654752f));
                v1 = 0.5f * v1 * (1.f + erff(v1 * 0.70710678118654752f));
                v2 = 0.5f * v2 * (1.f + erff(v2 * 0.70710678118654752f));
                v3 = 0.5f * v3 * (1.f + erff(v3 * 0.70710678118654752f));
                if (col >= HIDC) { v0 = v2 = 0.f; }
                if (col + 1 >= HIDC) { v1 = v3 = 0.f; }
                *(__half2*)(s_h + (m0 + g) * 120 + col)     = __floats2half2_rn(v0, v1);
                *(__half2*)(s_h + (m0 + g + 8) * 120 + col) = __floats2half2_rn(v2, v3);
            }
        }
    }
    __syncthreads();

    // MMA2: W0[64][49] = h[64][112] @ w2
    {
        int mg = wid & 3, ng = wid >> 2;
        int m0 = mg * 16;
        float e[2][4];
        #pragma unroll
        for (int t = 0; t < 2; t++)
            #pragma unroll
            for (int q = 0; q < 4; q++) e[t][q] = 0.f;
        for (int ks = 0; ks < 7; ks++) {
            const __half* ap = s_h + (m0 + g) * 120 + ks * 16 + 2 * t4;
            unsigned a0 = *(const unsigned*)ap;
            unsigned a1 = *(const unsigned*)(ap + 8 * 120);
            unsigned a2 = *(const unsigned*)(ap + 8);
            unsigned a3 = *(const unsigned*)(ap + 8 * 120 + 8);
            #pragma unroll
            for (int t = 0; t < 2; t++) {
                int n8 = ng * 2 + t;
                if (n8 < 7) {
                    uint2 v = g_w2F[((n8 * 7 + ks) << 5) + lane];
                    mma_f16(e[t], a0, a1, a2, a3, v.x, v.y);
                }
            }
        }
        #pragma unroll
        for (int t = 0; t < 2; t++) {
            int n8 = ng * 2 + t;
            if (n8 < 7) {
                int col = n8 * 8 + 2 * t4;
                int row0 = r0 + m0 + g;
                if (col < KEEPEDC) {
                    g_W0[(size_t)row0 * KEEPEDC + col]       = e[t][0] + s_b2[col];
                    g_W0[(size_t)(row0 + 8) * KEEPEDC + col] = e[t][2] + s_b2[col];
                }
                if (col + 1 < KEEPEDC) {
                    g_W0[(size_t)row0 * KEEPEDC + col + 1]       = e[t][1] + s_b2[col + 1];
                    g_W0[(size_t)(row0 + 8) * KEEPEDC + col + 1] = e[t][3] + s_b2[col + 1];
                }
            }
        }
    }
}

// ---------------- K6: attn_y tiled GEMM ----------------
__global__ __launch_bounds__(256) void k_attn_y(const float* __restrict__ img) {
    __shared__ float s_x[32 * 68];
    __shared__ float s_g[32 * 68];
    __shared__ int   s_off[64];
    __shared__ float s_inv[64];
    int tid = threadIdx.x;
    int r0 = blockIdx.x * 64;
    if (tid < 64) {
        int tok = r0 + tid;
        int b = tok / NSP; int j = tok - b * NSP;
        s_off[tid] = (b * LVC + 1 + j) * CCH;
        s_inv[tid] = g_inv_img[b * LVC + 1 + j];
    }
    __syncthreads();
    int tx = tid & 15, ty = tid >> 4;
    int i0 = tx * 4, t0 = ty * 4;
    float acc[4][4];
    #pragma unroll
    for (int a = 0; a < 4; a++)
        #pragma unroll
        for (int c = 0; c < 4; c++) acc[a][c] = 0.f;
    for (int c0 = 0; c0 < CCH; c0 += 32) {
        {
            int tk = tid >> 2; int cc0 = (tid & 3) * 8;
            const float* p = img + s_off[tk] + c0 + cc0;
            float4 v0 = *(const float4*)p;
            float4 v1 = *(const float4*)(p + 4);
            s_x[(cc0 + 0) * 68 + tk] = v0.x; s_x[(cc0 + 1) * 68 + tk] = v0.y;
            s_x[(cc0 + 2) * 68 + tk] = v0.z; s_x[(cc0 + 3) * 68 + tk] = v0.w;
            s_x[(cc0 + 4) * 68 + tk] = v1.x; s_x[(cc0 + 5) * 68 + tk] = v1.y;
            s_x[(cc0 + 6) * 68 + tk] = v1.z; s_x[(cc0 + 7) * 68 + tk] = v1.w;
        }
        {
            int cc = tid >> 3; int ii = (tid & 7) * 8;
            const float* p = g_gloT + (size_t)(c0 + cc) * NCAPC + ii;
            *(float4*)(s_g + cc * 68 + ii)     = *(const float4*)p;
            *(float4*)(s_g + cc * 68 + ii + 4) = *(const float4*)(p + 4);
        }
        __syncthreads();
        for (int cc = 0; cc < 32; cc++) {
            float4 gv = *(const float4*)(s_g + cc * 68 + i0);
            float4 xv = *(const float4*)(s_x + cc * 68 + t0);
            float xa[4] = {xv.x, xv.y, xv.z, xv.w};
            float gb[4] = {gv.x, gv.y, gv.z, gv.w};
            #pragma unroll
            for (int a = 0; a < 4; a++)
                #pragma unroll
                for (int c = 0; c < 4; c++) acc[a][c] += xa[a] * gb[c];
        }
        __syncthreads();
    }
    #pragma unroll
    for (int a = 0; a < 4; a++) {
        float inv = s_inv[t0 + a];
        #pragma unroll
        for (int c = 0; c < 4; c++)
            g_attn_y[(size_t)(i0 + c) * (BB * NSP) + r0 + t0 + a] = acc[a][c] * inv;
    }
}

// ---------------- K7: per-pair fused kernel (unchanged from R13) ----------------
#define OFF_STH 0
#define OFF_WH  13260
#define OFF_G   13260
#define OFF_AC  20172
#define OFF_SCORE 25268
#define OFF_ORDER (OFF_SCORE + 196)
#define OFF_WNON  (OFF_ORDER + 196)
#define OFF_INVN  (OFF_WNON + 98)
#define OFF_CM (OFF_INVN + 56)
#define OFF_CZ (OFF_CM + 51)
#define OFF_RM (OFF_CZ + 51)
#define OFF_RZ (OFF_RM + 32)
#define OFF_RED (OFF_RZ + 32)
#define OFF_SCAL (OFF_RED + 16)
#define SMEM_FLOATS (OFF_SCAL + 8)

__global__ __launch_bounds__(512, 2) void k_pair(
    const float* __restrict__ img,
    const float* __restrict__ aggr_scale_p,
    const float* __restrict__ temp_p,
    float* __restrict__ out) {
    extern __shared__ float sm[];
    __half* s_sth  = (__half*)(sm + OFF_STH);
    __half* s_Wh   = (__half*)(sm + OFF_WH);
    float* s_AC    = sm + OFF_AC;
    float* s_G     = sm + OFF_G;
    float* s_score = sm + OFF_SCORE;
    int*   s_order = (int*)(sm + OFF_ORDER);
    float* s_wnon  = sm + OFF_WNON;
    float* s_invn  = sm + OFF_INVN;
    float* s_cm    = sm + OFF_CM;
    float* s_cz    = sm + OFF_CZ;
    float* s_rm    = sm + OFF_RM;
    float* s_rz    = sm + OFF_RZ;
    float* s_red   = sm + OFF_RED;
    float* s_scal  = sm + OFF_SCAL;

    int pair = blockIdx.x;
    int i = pair & (NCAPC - 1);
    int b = pair >> 6;
    int tid = threadIdx.x;
    int lane = tid & 31, wid = tid >> 5;
    int g = lane >> 2, t4 = lane & 3;

    if (tid < NSP) {
        s_score[tid] = g_attn_x[b * NSP + tid]
                     + g_attn_y[(size_t)i * (BB * NSP) + b * NSP + tid];
    }
    __syncthreads();

    if (tid < NSP) {
        float sj = s_score[tid];
        int rank = 0;
        for (int j2 = 0; j2 < NSP; j2++) {
            float s2 = s_score[j2];
            rank += (s2 > sj) || (s2 == sj && j2 < tid);
        }
        s_order[rank] = tid;
    }
    __syncthreads();

    if (tid < 98) s_wnon[tid] = s_score[s_order[NKEEP + tid]];
    __syncthreads();
    if (wid == 0) {
        float m = -INFINITY;
        for (int t = lane; t < 98; t += 32) m = fmaxf(m, s_wnon[t]);
        m = warpReduceMax(m);
        if (lane == 0) s_scal[0] = m;
    }
    __syncthreads();
    if (tid < 98) s_wnon[tid] = expf(s_wnon[tid] - s_scal[0]);
    __syncthreads();
    if (wid == 0) {
        float z = 0.f;
        for (int t = lane; t < 98; t += 32) z += s_wnon[t];
        z = warpReduceSum(z);
        if (lane == 0) s_scal[1] = 1.f / z;
    }
    {
        float ascale = aggr_scale_p[0];
        for (int idx = tid; idx < NKEEP * KEEPEDC; idx += 512) {
            int jj = idx / KEEPEDC; int k = idx - jj * KEEPEDC;
            s_AC[jj * 52 + k] = g_W0[((size_t)b * NSP + s_order[jj]) * KEEPEDC + k] * ascale;
        }
        for (int idx = tid; idx < 6912; idx += 512) sm[OFF_WH + idx] = 0.f;
    }
    __syncthreads();
    for (int k = wid; k < KEEPEDC; k += 16) {
        float km = -INFINITY;
        for (int jj = lane; jj < NKEEP; jj += 32) km = fmaxf(km, s_AC[jj * 52 + k]);
        km = warpReduceMax(km);
        float kz = 0.f;
        for (int jj = lane; jj < NKEEP; jj += 32) {
            float e = expf(s_AC[jj * 52 + k] - km);
            s_AC[jj * 52 + k] = e; kz += e;
        }
        kz = warpReduceSum(kz);
        float inv = 1.f / kz;
        for (int jj = lane; jj < NKEEP; jj += 32) s_AC[jj * 52 + k] *= inv;
    }
    __syncthreads();
    {
        for (int idx = tid; idx < NKEEP * KEEPEDC; idx += 512) {
            int jj = idx / KEEPEDC; int r = idx - jj * KEEPEDC;
            s_Wh[r * 216 + s_order[jj]] = __float2half(s_AC[jj * 52 + r]);
        }
        float invz = s_scal[1];
        if (tid < 98)
            s_Wh[49 * 216 + s_order[NKEEP + tid]] = __float2half(s_wnon[tid] * invz);
        s_sth[tid] = __float2half(img[(size_t)b * LVC * CCH + tid]);
    }
    __syncthreads();

    {
        int mg = wid & 1, ng = wid >> 1;
        int mb0 = mg * 32;
        const uint2* Bf = g_imgF + (size_t)b * 64 * 13 * 32;
        for (int rr = 0; rr < 4; rr++) {
            int n0 = ng * 64 + rr * 16;
            float d[2][2][4];
            #pragma unroll
            for (int mt = 0; mt < 2; mt++)
                #pragma unroll
                for (int nt = 0; nt < 2; nt++)
                    #pragma unroll
                    for (int q = 0; q < 4; q++) d[mt][nt][q] = 0.f;
            for (int ks = 0; ks < 13; ks++) {
                int kk = ks * 16;
                unsigned a[2][4];
                #pragma unroll
                for (int mt = 0; mt < 2; mt++) {
                    const __half* wp = s_Wh + (mb0 + mt * 16 + g) * 216 + kk + 2 * t4;
                    a[mt][0] = *(const unsigned*)wp;
                    a[mt][1] = *(const unsigned*)(wp + 8 * 216);
                    a[mt][2] = *(const unsigned*)(wp + 8);
                    a[mt][3] = *(const unsigned*)(wp + 8 * 216 + 8);
                }
                #pragma unroll
                for (int nt = 0; nt < 2; nt++) {
                    int n8 = (n0 + nt * 8) >> 3;
                    uint2 v = Bf[((n8 * 13 + ks) << 5) + lane];
                    mma_f16(d[0][nt], a[0][0], a[0][1], a[0][2], a[0][3], v.x, v.y);
                    mma_f16(d[1][nt], a[1][0], a[1][1], a[1][2], a[1][3], v.x, v.y);
                }
            }
            #pragma unroll
            for (int mt = 0; mt < 2; mt++) {
                int mr = mb0 + mt * 16 + g;
                #pragma unroll
                for (int nt = 0; nt < 2; nt++) {
                    int nb = n0 + nt * 8 + 2 * t4;
                    if (mr + 1 <= 50)
                        *(__half2*)(s_sth + (mr + 1) * 520 + nb) = __floats2half2_rn(d[mt][nt][0], d[mt][nt][1]);
                    if (mr + 9 <= 50)
                        *(__half2*)(s_sth + (mr + 9) * 520 + nb) = __floats2half2_rn(d[mt][nt][2], d[mt][nt][3]);
                }
            }
        }
    }
    __syncthreads();

    for (int l = wid; l < 51; l += 16) {
        float ssq = 0.f;
        for (int c = lane; c < CCH; c += 32) {
            float v = __half2float(s_sth[l * 520 + c]); ssq += v * v;
        }
        ssq = warpReduceSum(ssq);
        if (lane == 0) s_invn[l] = 1.f / fmaxf(sqrtf(ssq), 1e-12f);
    }
    __syncthreads();

    {
        bool act = (wid < 12);
        int mg = wid % 3, ng = wid / 3;
        int mb0 = mg * 32;
        int n0 = ng * 16;
        int ntiles = (ng == 3) ? 1 : 2;
        float d[2][2][4];
        #pragma unroll
        for (int mt = 0; mt < 2; mt++)
            #pragma unroll
            for (int nt = 0; nt < 2; nt++)
                #pragma unroll
                for (int q = 0; q < 4; q++) d[mt][nt][q] = 0.f;
        if (act) {
            const uint4* Af = g_catF + (size_t)i * 6 * 32 * 32;
            for (int ks = 0; ks < 32; ks++) {
                uint4 a0 = Af[(((mg * 2 + 0) * 32 + ks) << 5) + lane];
                uint4 a1 = Af[(((mg * 2 + 1) * 32 + ks) << 5) + lane];
                int kg = ks * 16;
                #pragma unroll
                for (int nt = 0; nt < 2; nt++) {
                    if (nt < ntiles) {
                        const __half* bp = s_sth + (size_t)(n0 + nt * 8 + g) * 520 + kg + 2 * t4;
                        unsigned b0 = *(const unsigned*)bp;
                        unsigned b1 = *(const unsigned*)(bp + 8);
                        mma_f16(d[0][nt], a0.x, a0.y, a0.z, a0.w, b0, b1);
                        mma_f16(d[1][nt], a1.x, a1.y, a1.z, a1.w, b0, b1);
                    }
                }
            }
        }
        if (act) {
            #pragma unroll
            for (int mt = 0; mt < 2; mt++) {
                int tr = mb0 + mt * 16 + g;
                #pragma unroll
                for (int nt = 0; nt < 2; nt++) {
                    if (nt < ntiles) {
                        int l0 = n0 + nt * 8 + 2 * t4;
                        if (l0 < 51)     s_G[tr * 51 + l0]           = d[mt][nt][0] * s_invn[l0];
                        if (l0 + 1 < 51) s_G[tr * 51 + l0 + 1]       = d[mt][nt][1] * s_invn[l0 + 1];
                        if (l0 < 51)     s_G[(tr + 8) * 51 + l0]     = d[mt][nt][2] * s_invn[l0];
                        if (l0 + 1 < 51) s_G[(tr + 8) * 51 + l0 + 1] = d[mt][nt][3] * s_invn[l0 + 1];
                    }
                }
            }
        }
    }
    __syncthreads();

    float invtemp = 1.f / temp_p[0];
    if (tid < 51) {
        int l = tid;
        float cm = -INFINITY;
        for (int t = 0; t < 32; t++) cm = fmaxf(cm, s_G[(32 + t) * 51 + l] * invtemp);
        float cz = 0.f;
        for (int t = 0; t < 32; t++) cz += expf(s_G[(32 + t) * 51 + l] * invtemp - cm);
        s_cm[l] = cm; s_cz[l] = cz;
    } else if (tid >= 64 && tid < 96) {
        int t = tid - 64;
        float rm = -INFINITY;
        for (int l = 0; l < 51; l++) rm = fmaxf(rm, s_G[(64 + t) * 51 + l] * invtemp);
        float rz = 0.f;
        for (int l = 0; l < 51; l++) rz += expf(s_G[(64 + t) * 51 + l] * invtemp - rm);
        s_rm[t] = rm; s_rz[t] = rz;
    }
    __syncthreads();
    float part = 0.f;
    for (int idx = tid; idx < 32 * 51; idx += 512) {
        int t = idx / 51; int l = idx - t * 51;
        float gg = s_G[t * 51 + l];
        float c2i = (gg >= 0.f) ? gg : 0.1f * gg;
        float li = s_G[(32 + t) * 51 + l] * invtemp;
        float lt = s_G[(64 + t) * 51 + l] * invtemp;
        float ai = expf(li - s_cm[l]) / s_cz[l];
        float at = expf(lt - s_rm[t]) / s_rz[t];
        part += c2i * (ai * (1.f / 51.f) + at * (1.f / 32.f));
    }
    part = warpReduceSum(part);
    if (lane == 0) s_red[wid] = part;
    __syncthreads();
    if (tid == 0) {
        float s = 0.f;
        for (int w = 0; w < 16; w++) s += s_red[w];
        out[b * NCAPC + i] = s;
    }
}

// ---------------- launch ----------------
extern "C" void kernel_launch(void* const* d_in, const int* in_sizes, int n_in,
                              void* d_out, int out_size) {
    const float* img    = (const float*)d_in[0];
    const float* cap    = (const float*)d_in[1];
    const float* gamma  = (const float*)d_in[3];
    const float* beta   = (const float*)d_in[4];
    const float* w1     = (const float*)d_in[5];
    const float* b1     = (const float*)d_in[6];
    const float* w2     = (const float*)d_in[7];
    const float* b2     = (const float*)d_in[8];
    const float* ascale = (const float*)d_in[9];
    const float* wi2t   = (const float*)d_in[10];
    const float* bi2t   = (const float*)d_in[11];
    const float* wt2i   = (const float*)d_in[12];
    const float* bt2i   = (const float*)d_in[13];
    const float* temp   = (const float*)d_in[14];
    float* out = (float*)d_out;

    cudaFuncSetAttribute(k_W0, cudaFuncAttributeMaxDynamicSharedMemorySize, W0_SMEM * 4);
    cudaFuncSetAttribute(k_pair, cudaFuncAttributeMaxDynamicSharedMemorySize, SMEM_FLOATS * 4);

    k_inv<<<BB * LVC, 128>>>(img);
    k_imgF<<<BB * 13, 512>>>(img);
    k_cap<<<NCAPC * LTC, 128>>>(cap);
    k_attnx<<<BB * NSP, 128>>>(img);
    k_w1F<<<52, 256>>>(w1);
    k_w2F<<<7, 256>>>(w2);
    k_wF<<<512, 256>>>(wi2t, wt2i);
    k_capW<<<NCAPC, 512>>>(bi2t, bt2i);
    k_catF<<<NCAPC * 6, 512>>>();
    k_W0<<<(BB * NSP) / 64, 512, W0_SMEM * 4>>>(img, gamma, beta, b1, b2);
    k_attn_y<<<(BB * NSP) / 64, 256>>>(img);
    k_pair<<<NCAPC * BB, 512, SMEM_FLOATS * 4>>>(img, ascale, temp, out);
}